// round 1
// baseline (speedup 1.0000x reference)
#include <cuda_runtime.h>
#include <cuda_bf16.h>

// ---------------------------------------------------------------------------
// Problem constants
// ---------------------------------------------------------------------------
#define NVOC 10000
#define NIN  1024
#define NHID 256
#define G3   768          // 3*NHID
#define TT   128
#define BB   64
#define MM   (TT*BB)      // 8192

// ---------------------------------------------------------------------------
// Device scratch (static allocations only — no cudaMalloc allowed)
// ---------------------------------------------------------------------------
__device__ float g_xg1  [MM * G3];     // GRU1 input gates
__device__ float g_xg2  [MM * G3];     // GRU2 input gates (emb part)
__device__ float g_hb2  [BB * G3];     // GRU2 constant input-gate part (h1 @ Wih2[:, :256]^T + bih2)
__device__ float g_h1   [BB * NHID];   // GRU1 final hidden
__device__ float g_preds[MM * NHID];   // GRU2 outputs per step
__device__ float g_WT1  [NHID * G3];   // Whh1 transposed -> [256][768]
__device__ float g_WT2  [NHID * G3];   // Whh2 transposed

// ---------------------------------------------------------------------------
// f32x2 packed FMA helpers (Blackwell: doubles fp32 FMA throughput vs FFMA-3reg)
// ---------------------------------------------------------------------------
__device__ __forceinline__ unsigned long long f2pack(float lo, float hi) {
    unsigned long long v;
    asm("mov.b64 %0, {%1, %2};" : "=l"(v) : "f"(lo), "f"(hi));
    return v;
}
__device__ __forceinline__ void f2unpack(unsigned long long v, float& lo, float& hi) {
    asm("mov.b64 {%0, %1}, %2;" : "=f"(lo), "=f"(hi) : "l"(v));
}
__device__ __forceinline__ void ffma2(unsigned long long& d, unsigned long long a,
                                      unsigned long long b) {
    asm("fma.rn.f32x2 %0, %1, %2, %3;" : "=l"(d) : "l"(a), "l"(b), "l"(d));
}

// ---------------------------------------------------------------------------
// 32x32 transpose: in [768][256] -> out [256][768]
// ---------------------------------------------------------------------------
__global__ void transpose_k(const float* __restrict__ in, float* __restrict__ out) {
    __shared__ float tile[32][33];
    int r0 = blockIdx.x * 32;   // over 768
    int c0 = blockIdx.y * 32;   // over 256
    for (int i = threadIdx.y; i < 32; i += 8)
        tile[i][threadIdx.x] = in[(r0 + i) * NHID + (c0 + threadIdx.x)];
    __syncthreads();
    for (int i = threadIdx.y; i < 32; i += 8)
        out[(c0 + i) * G3 + (r0 + threadIdx.x)] = tile[threadIdx.x][i];
}

// ---------------------------------------------------------------------------
// NT SGEMM:  C[m,n] = sum_k A[m,k] * Bw[n,k]  (+ bias[n])
// A rows optionally gathered through tok[] (embedding fuse).
// Tiles: 128x128x8, 256 threads, 8x8 per thread, f32x2 accumulation.
// ---------------------------------------------------------------------------
__global__ void __launch_bounds__(256)
sgemm_nt(const float* __restrict__ A, int lda,
         const float* __restrict__ Bw, int ldb,
         const float* __restrict__ bias,
         float* __restrict__ C, int ldc,
         const int* __restrict__ tok,
         int M, int N, int K)
{
    __shared__ __align__(16) float As[8][132];
    __shared__ __align__(16) float Bs[8][128];

    const int tid  = threadIdx.x;
    const int row0 = blockIdx.y * 128;
    const int col0 = blockIdx.x * 128;

    // global load mapping: li = row within tile, lk = 4-float chunk of K
    const int li = tid >> 1;
    const int lk = (tid & 1) * 4;

    int ar = row0 + li;
    if (ar >= M) ar = M - 1;                 // clamp (loads valid, stores guarded)
    if (tok) ar = tok[ar];                   // fused embedding gather
    const float* Ap = A + (size_t)ar * lda + lk;

    int brn = col0 + li;
    const bool bval = (brn < N);
    const float* Bp = Bw + (size_t)(bval ? brn : 0) * ldb + lk;

    const int ty = tid >> 4;   // 0..15
    const int tx = tid & 15;   // 0..15

    unsigned long long acc2[8][4];
#pragma unroll
    for (int r = 0; r < 8; r++)
#pragma unroll
        for (int c = 0; c < 4; c++) acc2[r][c] = 0ull;   // bits of {0.f,0.f}

    for (int k0 = 0; k0 < K; k0 += 8) {
        float4 av = *(const float4*)(Ap + k0);
        float4 bv = bval ? *(const float4*)(Bp + k0) : make_float4(0.f, 0.f, 0.f, 0.f);

        __syncthreads();
        As[lk + 0][li] = av.x; As[lk + 1][li] = av.y;
        As[lk + 2][li] = av.z; As[lk + 3][li] = av.w;
        Bs[lk + 0][li] = bv.x; Bs[lk + 1][li] = bv.y;
        Bs[lk + 2][li] = bv.z; Bs[lk + 3][li] = bv.w;
        __syncthreads();

#pragma unroll
        for (int kk = 0; kk < 8; kk++) {
            float4 a0 = *(const float4*)&As[kk][ty * 8];
            float4 a1 = *(const float4*)&As[kk][ty * 8 + 4];
            const unsigned long long* bp =
                (const unsigned long long*)&Bs[kk][tx * 8];
            unsigned long long b0 = bp[0], b1 = bp[1], b2 = bp[2], b3 = bp[3];
            float arr[8] = {a0.x, a0.y, a0.z, a0.w, a1.x, a1.y, a1.z, a1.w};
#pragma unroll
            for (int r = 0; r < 8; r++) {
                unsigned long long ad = f2pack(arr[r], arr[r]);
                ffma2(acc2[r][0], ad, b0);
                ffma2(acc2[r][1], ad, b1);
                ffma2(acc2[r][2], ad, b2);
                ffma2(acc2[r][3], ad, b3);
            }
        }
    }

    const bool fullcol = (col0 + 128 <= N);
#pragma unroll
    for (int r = 0; r < 8; r++) {
        int row = row0 + ty * 8 + r;
        if (row >= M) continue;
        float* Cp = C + (size_t)row * ldc + col0 + tx * 8;
        float v[8];
#pragma unroll
        for (int c = 0; c < 4; c++) f2unpack(acc2[r][c], v[2 * c], v[2 * c + 1]);
        if (fullcol) {
            if (bias) {
#pragma unroll
                for (int c = 0; c < 8; c++) v[c] += bias[col0 + tx * 8 + c];
            }
            *(float4*)(Cp)     = make_float4(v[0], v[1], v[2], v[3]);
            *(float4*)(Cp + 4) = make_float4(v[4], v[5], v[6], v[7]);
        } else {
#pragma unroll
            for (int c = 0; c < 8; c++) {
                int col = col0 + tx * 8 + c;
                if (col < N) Cp[c] = v[c] + (bias ? bias[col] : 0.f);
            }
        }
    }
}

// ---------------------------------------------------------------------------
// GRU scan. One CTA handles 2 independent batch lanes for all 128 steps.
// grid = 32 CTAs, 192 threads. Per step:
//   phase 1: hg = h @ WhhT (+bhh), thread q owns output quad [4q..4q+3], both batches
//   phase 2: gate nonlinearities + hidden update (512 tasks)
// xg: precomputed input gates [T*B, 768]; hb (optional): constant per-batch
// additive gate term [B, 768]. preds (optional): [T*B, 256] per-step hidden out.
// ---------------------------------------------------------------------------
__global__ void __launch_bounds__(192)
gru_scan(const float* __restrict__ xg,
         const float* __restrict__ hb,
         const float* __restrict__ WT,     // [256][768]
         const float* __restrict__ bhh,    // [768]
         float* __restrict__ hfin,         // [64,256] or null
         float* __restrict__ preds,        // [T*B,256] or null
         float* __restrict__ tail)         // d_out tail or null
{
    __shared__ float sh0[NHID];
    __shared__ float sh1[NHID];
    __shared__ __align__(16) float hg[2][G3];

    const int tid = threadIdx.x;          // 0..191
    const int b0  = blockIdx.x * 2;

    for (int k = tid; k < NHID; k += 192) { sh0[k] = 0.f; sh1[k] = 0.f; }
    __syncthreads();

    const int j = tid * 4;                 // output quad
    const float4 bh4 = *(const float4*)(bhh + j);
    const float* wp = WT + j;

    for (int t = 0; t < TT; t++) {
        // ---- phase 1: recurrent GEMV, quad j, both batches ----
        float4 a0 = bh4, a1 = bh4;
#pragma unroll 8
        for (int k = 0; k < NHID; k++) {
            float4 w = *(const float4*)(wp + (size_t)k * G3);
            float h0 = sh0[k], h1v = sh1[k];
            a0.x += w.x * h0;  a0.y += w.y * h0;
            a0.z += w.z * h0;  a0.w += w.w * h0;
            a1.x += w.x * h1v; a1.y += w.y * h1v;
            a1.z += w.z * h1v; a1.w += w.w * h1v;
        }
        *(float4*)&hg[0][j] = a0;
        *(float4*)&hg[1][j] = a1;
        __syncthreads();

        // ---- phase 2: gates + update ----
        for (int idx = tid; idx < 2 * NHID; idx += 192) {
            int b = idx >> 8;
            int c = idx & 255;
            int m = t * BB + b0 + b;
            const float* xp = xg + (size_t)m * G3;
            float gr = xp[c], gz = xp[NHID + c], gn = xp[2 * NHID + c];
            if (hb) {
                const float* hp = hb + (size_t)(b0 + b) * G3;
                gr += hp[c]; gz += hp[NHID + c]; gn += hp[2 * NHID + c];
            }
            float r = 1.f / (1.f + __expf(-(gr + hg[b][c])));
            float z = 1.f / (1.f + __expf(-(gz + hg[b][NHID + c])));
            float n = tanhf(gn + r * hg[b][2 * NHID + c]);
            float ho = b ? sh1[c] : sh0[c];
            float hn = (1.f - z) * n + z * ho;
            if (b) sh1[c] = hn; else sh0[c] = hn;
            if (preds) preds[(size_t)m * NHID + c] = hn;
        }
        __syncthreads();
    }

    // final hidden out
    for (int idx = tid; idx < 2 * NHID; idx += 192) {
        int b = idx >> 8;
        int c = idx & 255;
        float v = b ? sh1[c] : sh0[c];
        if (hfin) hfin[(size_t)(b0 + b) * NHID + c] = v;
        if (tail) tail[(size_t)(b0 + b) * NHID + c] = v;
    }
}

// ---------------------------------------------------------------------------
// Launcher
// ---------------------------------------------------------------------------
extern "C" void kernel_launch(void* const* d_in, const int* in_sizes, int n_in,
                              void* d_out, int out_size)
{
    const int*   tokens = (const int*)  d_in[0];
    const float* E      = (const float*)d_in[1];
    const float* Wih1   = (const float*)d_in[2];
    const float* Whh1   = (const float*)d_in[3];
    const float* bih1   = (const float*)d_in[4];
    const float* bhh1   = (const float*)d_in[5];
    const float* Wih2   = (const float*)d_in[6];
    const float* Whh2   = (const float*)d_in[7];
    const float* bih2   = (const float*)d_in[8];
    const float* bhh2   = (const float*)d_in[9];
    // d_in[10..14] = Wh, bh, Wi, bi, w_att : provably dead (softmax weights sum
    // to 1 over a constant value h1, so the attention context == h1 exactly).
    const float* Wd     = (const float*)d_in[15];
    const float* bd     = (const float*)d_in[16];
    float* out = (float*)d_out;

    float *xg1, *xg2, *hb2, *h1, *preds, *WT1, *WT2;
    cudaGetSymbolAddress((void**)&xg1,   g_xg1);
    cudaGetSymbolAddress((void**)&xg2,   g_xg2);
    cudaGetSymbolAddress((void**)&hb2,   g_hb2);
    cudaGetSymbolAddress((void**)&h1,    g_h1);
    cudaGetSymbolAddress((void**)&preds, g_preds);
    cudaGetSymbolAddress((void**)&WT1,   g_WT1);
    cudaGetSymbolAddress((void**)&WT2,   g_WT2);

    float* tail = nullptr;
    if (out_size >= MM * NVOC + BB * NHID) tail = out + (size_t)MM * NVOC;

    // 1. transpose recurrent weights for coalesced GEMV
    transpose_k<<<dim3(24, 8), dim3(32, 8)>>>(Whh1, WT1);
    transpose_k<<<dim3(24, 8), dim3(32, 8)>>>(Whh2, WT2);

    // 2. input-gate GEMMs (embedding gather fused)
    sgemm_nt<<<dim3(6, 64), 256>>>(E, NIN, Wih1, NIN, bih1,
                                   xg1, G3, tokens, MM, G3, NIN);
    sgemm_nt<<<dim3(6, 64), 256>>>(E, NIN, Wih2 + NHID, NHID + NIN, nullptr,
                                   xg2, G3, tokens, MM, G3, NIN);

    // 3. GRU1 scan -> h1 (and hidden-state output tail)
    gru_scan<<<32, 192>>>(xg1, nullptr, WT1, bhh1, h1, nullptr, tail);

    // 4. constant GRU2 gate part: h1 @ Wih2[:, :256]^T + bih2
    sgemm_nt<<<dim3(6, 1), 256>>>(h1, NHID, Wih2, NHID + NIN, bih2,
                                  hb2, G3, nullptr, BB, G3, NHID);

    // 5. GRU2 scan -> preds
    gru_scan<<<32, 192>>>(xg2, hb2, WT2, bhh2, nullptr, preds, nullptr);

    // 6. decoder: logits = preds @ Wd^T + bd
    sgemm_nt<<<dim3(79, 64), 256>>>(preds, NHID, Wd, NHID, bd,
                                    out, NVOC, nullptr, MM, NVOC, NHID);
}

// round 2
// speedup vs baseline: 1.8467x; 1.8467x over previous
#include <cuda_runtime.h>
#include <cuda_bf16.h>

// ---------------------------------------------------------------------------
// Problem constants
// ---------------------------------------------------------------------------
#define NVOC 10000
#define NIN  1024
#define NHID 256
#define G3   768          // 3*NHID
#define TT   128
#define BB   64
#define MM   (TT*BB)      // 8192

#define SCAN_CTAS 64      // one CTA per 4 hidden columns
#define SCAN_THREADS 192

// ---------------------------------------------------------------------------
// Device scratch (static allocations only — no cudaMalloc allowed)
// ---------------------------------------------------------------------------
__device__ float g_xg1  [MM * G3];     // GRU1 input gates
__device__ float g_xg2  [MM * G3];     // GRU2 input gates (emb part)
__device__ float g_hb2  [BB * G3];     // GRU2 constant gate part
__device__ float g_h1   [BB * NHID];   // GRU1 final hidden
__device__ float g_preds[MM * NHID];   // GRU2 outputs per step
__device__ float g_WT1  [NHID * G3];   // Whh1 transposed -> [256][768]
__device__ float g_WT2  [NHID * G3];   // Whh2 transposed
__device__ float g_hsg  [NHID * BB];   // hidden broadcast buffer, float2 [128][64]
__device__ int   g_cnt1 [TT];          // scan1 step barrier counters
__device__ int   g_cnt2 [TT];          // scan2 step barrier counters

// ---------------------------------------------------------------------------
// f32x2 packed FMA helpers
// ---------------------------------------------------------------------------
__device__ __forceinline__ unsigned long long f2pack(float lo, float hi) {
    unsigned long long v;
    asm("mov.b64 %0, {%1, %2};" : "=l"(v) : "f"(lo), "f"(hi));
    return v;
}
__device__ __forceinline__ void f2unpack(unsigned long long v, float& lo, float& hi) {
    asm("mov.b64 {%0, %1}, %2;" : "=f"(lo), "=f"(hi) : "l"(v));
}
__device__ __forceinline__ void ffma2(unsigned long long& d, unsigned long long a,
                                      unsigned long long b) {
    asm("fma.rn.f32x2 %0, %1, %2, %3;" : "=l"(d) : "l"(a), "l"(b), "l"(d));
}

// ---------------------------------------------------------------------------
// init: zero the step-barrier counters (graph replays reuse them)
// ---------------------------------------------------------------------------
__global__ void init_cnt() {
    int i = threadIdx.x;
    if (i < TT) { g_cnt1[i] = 0; g_cnt2[i] = 0; }
}

// ---------------------------------------------------------------------------
// 32x32 transpose: in [768][256] -> out [256][768]
// ---------------------------------------------------------------------------
__global__ void transpose_k(const float* __restrict__ in, float* __restrict__ out) {
    __shared__ float tile[32][33];
    int r0 = blockIdx.x * 32;   // over 768
    int c0 = blockIdx.y * 32;   // over 256
    for (int i = threadIdx.y; i < 32; i += 8)
        tile[i][threadIdx.x] = in[(r0 + i) * NHID + (c0 + threadIdx.x)];
    __syncthreads();
    for (int i = threadIdx.y; i < 32; i += 8)
        out[(c0 + i) * G3 + (r0 + threadIdx.x)] = tile[threadIdx.x][i];
}

// ---------------------------------------------------------------------------
// NT SGEMM:  C[m,n] = sum_k A[m,k] * Bw[n,k]  (+ bias[n])   (unchanged)
// ---------------------------------------------------------------------------
__global__ void __launch_bounds__(256)
sgemm_nt(const float* __restrict__ A, int lda,
         const float* __restrict__ Bw, int ldb,
         const float* __restrict__ bias,
         float* __restrict__ C, int ldc,
         const int* __restrict__ tok,
         int M, int N, int K)
{
    __shared__ __align__(16) float As[8][132];
    __shared__ __align__(16) float Bs[8][128];

    const int tid  = threadIdx.x;
    const int row0 = blockIdx.y * 128;
    const int col0 = blockIdx.x * 128;

    const int li = tid >> 1;
    const int lk = (tid & 1) * 4;

    int ar = row0 + li;
    if (ar >= M) ar = M - 1;
    if (tok) ar = tok[ar];
    const float* Ap = A + (size_t)ar * lda + lk;

    int brn = col0 + li;
    const bool bval = (brn < N);
    const float* Bp = Bw + (size_t)(bval ? brn : 0) * ldb + lk;

    const int ty = tid >> 4;
    const int tx = tid & 15;

    unsigned long long acc2[8][4];
#pragma unroll
    for (int r = 0; r < 8; r++)
#pragma unroll
        for (int c = 0; c < 4; c++) acc2[r][c] = 0ull;

    for (int k0 = 0; k0 < K; k0 += 8) {
        float4 av = *(const float4*)(Ap + k0);
        float4 bv = bval ? *(const float4*)(Bp + k0) : make_float4(0.f, 0.f, 0.f, 0.f);

        __syncthreads();
        As[lk + 0][li] = av.x; As[lk + 1][li] = av.y;
        As[lk + 2][li] = av.z; As[lk + 3][li] = av.w;
        Bs[lk + 0][li] = bv.x; Bs[lk + 1][li] = bv.y;
        Bs[lk + 2][li] = bv.z; Bs[lk + 3][li] = bv.w;
        __syncthreads();

#pragma unroll
        for (int kk = 0; kk < 8; kk++) {
            float4 a0 = *(const float4*)&As[kk][ty * 8];
            float4 a1 = *(const float4*)&As[kk][ty * 8 + 4];
            const unsigned long long* bp =
                (const unsigned long long*)&Bs[kk][tx * 8];
            unsigned long long b0 = bp[0], b1 = bp[1], b2 = bp[2], b3 = bp[3];
            float arr[8] = {a0.x, a0.y, a0.z, a0.w, a1.x, a1.y, a1.z, a1.w};
#pragma unroll
            for (int r = 0; r < 8; r++) {
                unsigned long long ad = f2pack(arr[r], arr[r]);
                ffma2(acc2[r][0], ad, b0);
                ffma2(acc2[r][1], ad, b1);
                ffma2(acc2[r][2], ad, b2);
                ffma2(acc2[r][3], ad, b3);
            }
        }
    }

    const bool fullcol = (col0 + 128 <= N);
#pragma unroll
    for (int r = 0; r < 8; r++) {
        int row = row0 + ty * 8 + r;
        if (row >= M) continue;
        float* Cp = C + (size_t)row * ldc + col0 + tx * 8;
        float v[8];
#pragma unroll
        for (int c = 0; c < 4; c++) f2unpack(acc2[r][c], v[2 * c], v[2 * c + 1]);
        if (fullcol) {
            if (bias) {
#pragma unroll
                for (int c = 0; c < 8; c++) v[c] += bias[col0 + tx * 8 + c];
            }
            *(float4*)(Cp)     = make_float4(v[0], v[1], v[2], v[3]);
            *(float4*)(Cp + 4) = make_float4(v[4], v[5], v[6], v[7]);
        } else {
#pragma unroll
            for (int c = 0; c < 8; c++) {
                int col = col0 + tx * 8 + c;
                if (col < N) Cp[c] = v[c] + (bias ? bias[col] : 0.f);
            }
        }
    }
}

// ---------------------------------------------------------------------------
// GRU scan v2: column-partitioned persistent kernel with chip spin-barrier.
//
// 64 CTAs, 192 threads. CTA i owns hidden cols [4i, 4i+4) => gate columns
// {g*256 + 4i + j}. Its 12-column WhhT slice lives in smem all 128 steps.
// Full h state kept in smem (float2 [128][64]); after each step every CTA
// publishes its 4 columns (2 float2 rows) to g_hsg, passes an atomic
// counter barrier, and refreshes its smem copy via __ldcg.
//
// Dyn smem layout:
//   [0, 12288)            float4 w_s[256][3]   (as ulonglong2 pairs)
//   [12288, 77824)        float2 hs [128][64]  (h pairs: hs[kk][b]=(h[b][2kk],h[b][2kk+1]))
//   [77824, 80896)        float4 sg [3][64]    (gate GEMV results)
// ---------------------------------------------------------------------------
#define SMEM_W   0
#define SMEM_HS  12288
#define SMEM_SG  77824
#define SMEM_SCAN 80896

__global__ void __launch_bounds__(SCAN_THREADS)
gru_scan2(const float* __restrict__ xg,
          const float* __restrict__ hb,      // [64][768] or null
          const float* __restrict__ WT,      // [256][768]
          const float* __restrict__ bhh,     // [768]
          float* __restrict__ hfin,          // [64][256] or null
          float* __restrict__ preds,         // [T*B][256] or null
          float* __restrict__ tail,          // d_out tail or null
          float* __restrict__ hsg,           // [128][64] float2 broadcast buf
          int*   __restrict__ cnt)           // [128]
{
    extern __shared__ char smem[];
    float4*           w_s = (float4*)(smem + SMEM_W);    // [k][q] -> k*3+q
    float2*           hs2 = (float2*)(smem + SMEM_HS);   // [kk][b] -> kk*64+b
    float4*           sg  = (float4*)(smem + SMEM_SG);   // [q][b] -> q*64+b

    const int tid = threadIdx.x;
    const int q   = tid >> 6;        // gate group 0..2
    const int b   = tid & 63;        // batch lane
    const int c0  = blockIdx.x * 4;  // owned hidden cols c0..c0+3
    const int kk0 = c0 >> 1;         // owned hs rows kk0, kk0+1

    // load WhhT slice: w_s[k][g] = WT[k][g*256 + c0 .. +3]
    for (int i = tid; i < 768; i += SCAN_THREADS) {
        int k = i / 3, g = i - 3 * k;
        w_s[k * 3 + g] = *(const float4*)(WT + (size_t)k * G3 + g * NHID + c0);
    }
    // zero h state
    for (int i = tid; i < 4096; i += SCAN_THREADS)
        ((float4*)hs2)[i] = make_float4(0.f, 0.f, 0.f, 0.f);

    const float4 bh4 = *(const float4*)(bhh + q * NHID + c0);
    const unsigned long long bhA = f2pack(bh4.x, bh4.y);
    const unsigned long long bhB = f2pack(bh4.z, bh4.w);

    // constant per-batch gate addend (GRU2 only)
    float4 hbr = make_float4(0.f,0.f,0.f,0.f), hbz = hbr, hbn = hbr;
    if (hb && tid < 64) {
        const float* hp = hb + (size_t)b * G3;
        hbr = *(const float4*)(hp + c0);
        hbz = *(const float4*)(hp + NHID + c0);
        hbn = *(const float4*)(hp + 2 * NHID + c0);
    }
    __syncthreads();

    float2* hsg2 = (float2*)hsg;

    for (int t = 0; t < TT; t++) {
        // prefetch this step's input gates (tid<64 only; independent of h)
        float4 xr, xz, xn;
        if (tid < 64) {
            const float* xp = xg + (size_t)(t * BB + b) * G3;
            xr = *(const float4*)(xp + c0);
            xz = *(const float4*)(xp + NHID + c0);
            xn = *(const float4*)(xp + 2 * NHID + c0);
        }

        // ---- GEMV: acc[c0..c0+3] for gate q, batch b  (all from smem) ----
        unsigned long long accA = bhA, accB = bhB;
#pragma unroll 4
        for (int kk = 0; kk < 128; kk++) {
            ulonglong2 w0 = *(const ulonglong2*)&w_s[(2 * kk)     * 3 + q];
            ulonglong2 w1 = *(const ulonglong2*)&w_s[(2 * kk + 1) * 3 + q];
            float2 h2 = hs2[kk * 64 + b];
            unsigned long long h0 = f2pack(h2.x, h2.x);
            unsigned long long h1 = f2pack(h2.y, h2.y);
            ffma2(accA, w0.x, h0);
            ffma2(accB, w0.y, h0);
            ffma2(accA, w1.x, h1);
            ffma2(accB, w1.y, h1);
        }
        float4 accv;
        f2unpack(accA, accv.x, accv.y);
        f2unpack(accB, accv.z, accv.w);
        sg[q * 64 + b] = accv;
        __syncthreads();

        // ---- gates + hidden update (one thread per batch) ----
        if (tid < 64) {
            float4 rr4 = sg[b];
            float4 zz4 = sg[64 + b];
            float4 nn4 = sg[128 + b];
            float2 ho01 = hs2[kk0 * 64 + b];
            float2 ho23 = hs2[(kk0 + 1) * 64 + b];
            const float* rr = (const float*)&rr4;
            const float* zz = (const float*)&zz4;
            const float* nn = (const float*)&nn4;
            const float* xrv = (const float*)&xr;
            const float* xzv = (const float*)&xz;
            const float* xnv = (const float*)&xn;
            const float* hrv = (const float*)&hbr;
            const float* hzv = (const float*)&hbz;
            const float* hnv = (const float*)&hbn;
            float ho[4] = {ho01.x, ho01.y, ho23.x, ho23.y};
            float hn[4];
#pragma unroll
            for (int j = 0; j < 4; j++) {
                float r = 1.f / (1.f + __expf(-(xrv[j] + hrv[j] + rr[j])));
                float z = 1.f / (1.f + __expf(-(xzv[j] + hzv[j] + zz[j])));
                float n = tanhf(xnv[j] + hnv[j] + r * nn[j]);
                hn[j] = (1.f - z) * n + z * ho[j];
            }
            if (preds)
                *(float4*)(preds + (size_t)(t * BB + b) * NHID + c0) =
                    make_float4(hn[0], hn[1], hn[2], hn[3]);
            if (t == TT - 1) {
                if (hfin)
                    *(float4*)(hfin + (size_t)b * NHID + c0) =
                        make_float4(hn[0], hn[1], hn[2], hn[3]);
                if (tail)
                    *(float4*)(tail + (size_t)b * NHID + c0) =
                        make_float4(hn[0], hn[1], hn[2], hn[3]);
            } else {
                hsg2[kk0 * 64 + b]       = make_float2(hn[0], hn[1]);
                hsg2[(kk0 + 1) * 64 + b] = make_float2(hn[2], hn[3]);
                __threadfence();   // release: publish h slice before arriving
            }
        }
        if (t == TT - 1) break;

        __syncthreads();
        if (tid == 0) {
            atomicAdd(cnt + t, 1);
            while (((volatile int*)cnt)[t] < SCAN_CTAS) {}
            __threadfence();   // acquire
        }
        __syncthreads();

        // refresh full h state from L2 (bypass L1: stale lines from last step)
        {
            const float4* src = (const float4*)hsg;
            float4* dst = (float4*)hs2;
            for (int i = tid; i < 4096; i += SCAN_THREADS)
                dst[i] = __ldcg(src + i);
        }
        __syncthreads();
    }
}

// ---------------------------------------------------------------------------
// Launcher
// ---------------------------------------------------------------------------
extern "C" void kernel_launch(void* const* d_in, const int* in_sizes, int n_in,
                              void* d_out, int out_size)
{
    const int*   tokens = (const int*)  d_in[0];
    const float* E      = (const float*)d_in[1];
    const float* Wih1   = (const float*)d_in[2];
    const float* Whh1   = (const float*)d_in[3];
    const float* bih1   = (const float*)d_in[4];
    const float* bhh1   = (const float*)d_in[5];
    const float* Wih2   = (const float*)d_in[6];
    const float* Whh2   = (const float*)d_in[7];
    const float* bih2   = (const float*)d_in[8];
    const float* bhh2   = (const float*)d_in[9];
    // d_in[10..14] = Wh, bh, Wi, bi, w_att : dead (softmax over constant => context == h1)
    const float* Wd     = (const float*)d_in[15];
    const float* bd     = (const float*)d_in[16];
    float* out = (float*)d_out;

    float *xg1, *xg2, *hb2, *h1, *preds, *WT1, *WT2, *hsg;
    int *cnt1, *cnt2;
    cudaGetSymbolAddress((void**)&xg1,   g_xg1);
    cudaGetSymbolAddress((void**)&xg2,   g_xg2);
    cudaGetSymbolAddress((void**)&hb2,   g_hb2);
    cudaGetSymbolAddress((void**)&h1,    g_h1);
    cudaGetSymbolAddress((void**)&preds, g_preds);
    cudaGetSymbolAddress((void**)&WT1,   g_WT1);
    cudaGetSymbolAddress((void**)&WT2,   g_WT2);
    cudaGetSymbolAddress((void**)&hsg,   g_hsg);
    cudaGetSymbolAddress((void**)&cnt1,  g_cnt1);
    cudaGetSymbolAddress((void**)&cnt2,  g_cnt2);

    static bool attr_set = false;
    if (!attr_set) {
        cudaFuncSetAttribute(gru_scan2,
                             cudaFuncAttributeMaxDynamicSharedMemorySize,
                             SMEM_SCAN);
        attr_set = true;
    }

    float* tail = nullptr;
    if (out_size >= MM * NVOC + BB * NHID) tail = out + (size_t)MM * NVOC;

    // 0. reset chip-barrier counters (graph replays)
    init_cnt<<<1, 256>>>();

    // 1. transpose recurrent weights
    transpose_k<<<dim3(24, 8), dim3(32, 8)>>>(Whh1, WT1);
    transpose_k<<<dim3(24, 8), dim3(32, 8)>>>(Whh2, WT2);

    // 2. input-gate GEMMs (embedding gather fused)
    sgemm_nt<<<dim3(6, 64), 256>>>(E, NIN, Wih1, NIN, bih1,
                                   xg1, G3, tokens, MM, G3, NIN);
    sgemm_nt<<<dim3(6, 64), 256>>>(E, NIN, Wih2 + NHID, NHID + NIN, nullptr,
                                   xg2, G3, tokens, MM, G3, NIN);

    // 3. GRU1 scan -> h1 (and hidden-state output tail)
    gru_scan2<<<SCAN_CTAS, SCAN_THREADS, SMEM_SCAN>>>(
        xg1, nullptr, WT1, bhh1, h1, nullptr, tail, hsg, cnt1);

    // 4. constant GRU2 gate part: h1 @ Wih2[:, :256]^T + bih2
    sgemm_nt<<<dim3(6, 1), 256>>>(h1, NHID, Wih2, NHID + NIN, bih2,
                                  hb2, G3, nullptr, BB, G3, NHID);

    // 5. GRU2 scan -> preds
    gru_scan2<<<SCAN_CTAS, SCAN_THREADS, SMEM_SCAN>>>(
        xg2, hb2, WT2, bhh2, nullptr, preds, nullptr, hsg, cnt2);

    // 6. decoder: logits = preds @ Wd^T + bd
    sgemm_nt<<<dim3(79, 64), 256>>>(preds, NHID, Wd, NHID, bd,
                                    out, NVOC, nullptr, MM, NVOC, NHID);
}

// round 5
// speedup vs baseline: 2.5389x; 1.3748x over previous
#include <cuda_runtime.h>
#include <cuda_bf16.h>
#include <cstdint>

// ---------------------------------------------------------------------------
// Problem constants
// ---------------------------------------------------------------------------
#define NVOC 10000
#define NIN  1024
#define NHID 256
#define G3   768
#define TT   128
#define BB   64
#define MM   (TT*BB)

#define SCAN_CTAS 64
#define SCAN_THREADS 192

// single dynamic smem symbol (type must match across all kernels)
extern __shared__ char dsmem[];

// ---------------------------------------------------------------------------
// Device scratch
// ---------------------------------------------------------------------------
__device__ float g_xg1  [MM * G3];
__device__ float g_xg2  [MM * G3];
__device__ float g_hb2  [BB * G3];
__device__ float g_h1   [BB * NHID];
__device__ float g_preds[MM * NHID];
__device__ float g_WT1  [NHID * G3];
__device__ float g_WT2  [NHID * G3];
__device__ float g_hsg  [2 * NHID * BB];
__device__ int   g_cnt1 [TT];
__device__ int   g_cnt2 [TT];

// ---------------------------------------------------------------------------
// Helpers
// ---------------------------------------------------------------------------
__device__ __forceinline__ uint32_t to_tf32_bits(float x) {
    float y;
    asm("cvt.rna.tf32.f32 %0, %1;" : "=f"(y) : "f"(x));
    return __float_as_uint(y);
}
__device__ __forceinline__ unsigned long long f2pack(float lo, float hi) {
    unsigned long long v;
    asm("mov.b64 %0, {%1, %2};" : "=l"(v) : "f"(lo), "f"(hi));
    return v;
}
__device__ __forceinline__ void f2unpack(unsigned long long v, float& lo, float& hi) {
    asm("mov.b64 {%0, %1}, %2;" : "=f"(lo), "=f"(hi) : "l"(v));
}
__device__ __forceinline__ void ffma2(unsigned long long& d, unsigned long long a,
                                      unsigned long long b) {
    asm("fma.rn.f32x2 %0, %1, %2, %3;" : "=l"(d) : "l"(a), "l"(b), "l"(d));
}
__device__ __forceinline__ void mma_tf32(float* d, uint32_t a0, uint32_t a1,
                                         uint32_t a2, uint32_t a3,
                                         uint32_t b0, uint32_t b1) {
    asm volatile(
        "mma.sync.aligned.m16n8k8.row.col.f32.tf32.tf32.f32 "
        "{%0,%1,%2,%3}, {%4,%5,%6,%7}, {%8,%9}, {%0,%1,%2,%3};"
        : "+f"(d[0]), "+f"(d[1]), "+f"(d[2]), "+f"(d[3])
        : "r"(a0), "r"(a1), "r"(a2), "r"(a3), "r"(b0), "r"(b1));
}

// ---------------------------------------------------------------------------
__global__ void init_cnt() {
    int i = threadIdx.x;
    if (i < TT) { g_cnt1[i] = 0; g_cnt2[i] = 0; }
}

__global__ void transpose_k(const float* __restrict__ in, float* __restrict__ out) {
    __shared__ float tile[32][33];
    int r0 = blockIdx.x * 32;
    int c0 = blockIdx.y * 32;
    for (int i = threadIdx.y; i < 32; i += 8)
        tile[i][threadIdx.x] = in[(r0 + i) * NHID + (c0 + threadIdx.x)];
    __syncthreads();
    for (int i = threadIdx.y; i < 32; i += 8)
        out[(c0 + i) * G3 + (r0 + threadIdx.x)] = tile[threadIdx.x][i];
}

// ---------------------------------------------------------------------------
// tf32 mma.sync GEMM:  C[m,n] = sum_k A[m,k]*Bw[n,k] (+bias[n])
// CTA 128x128, BK=32 double-buffered. 8 warps, warp grid 4m x 2n (32x64 tiles).
// Smem layout (both A and B, [row][col] within a 128x32 chunk):
//   addr(r,c) = r*32 + (c&3) + 4*((c>>2) ^ (r&7))
// -> STS.128 staging stores and all fragment LDS.32 reads are conflict-free.
// ---------------------------------------------------------------------------
#define GM_THREADS 256
#define GM_SMEM    65536

__global__ void __launch_bounds__(GM_THREADS, 1)
gemm_mma(const float* __restrict__ A, int lda,
         const float* __restrict__ Bw, int ldb,
         const float* __restrict__ bias,
         float* __restrict__ C, int ldc,
         const int* __restrict__ tok,
         int M, int N, int K)
{
    float* smem = (float*)dsmem;
    float* Ab[2] = {smem,         smem + 4096};
    float* Bb[2] = {smem + 8192,  smem + 12288};

    const int tid  = threadIdx.x;
    const int wid  = tid >> 5, lane = tid & 31;
    const int wm   = wid >> 1;        // 0..3
    const int wn   = wid & 1;         // 0..1
    const int gid  = lane >> 2;       // 0..7
    const int tig  = lane & 3;        // 0..3
    const int row0 = blockIdx.y * 128, col0 = blockIdx.x * 128;

    // staging: thread -> rows r0+32*ps, cols c0..c0+3
    const int sr = tid >> 3;          // 0..31
    const int sc = (tid & 7) * 4;     // 0..28
    const float* Aptr[4];
    const float* Bptr[4];
#pragma unroll
    for (int ps = 0; ps < 4; ps++) {
        int ar = row0 + sr + ps * 32;
        if (ar >= M) ar = M - 1;
        if (tok) ar = tok[ar];
        Aptr[ps] = A + (size_t)ar * lda + sc;
        int br = col0 + sr + ps * 32;
        if (br >= N) br = N - 1;
        Bptr[ps] = Bw + (size_t)br * ldb + sc;
    }
    // swizzled store offset within a chunk (same formula for A and B)
    uint32_t stOff[4];
#pragma unroll
    for (int ps = 0; ps < 4; ps++) {
        int r = sr + ps * 32;
        stOff[ps] = r * 32 + 4 * ((sc >> 2) ^ (r & 7));
    }

    float4 aR[4], bR[4];
#pragma unroll
    for (int ps = 0; ps < 4; ps++) {
        aR[ps] = *(const float4*)(Aptr[ps]);
        bR[ps] = *(const float4*)(Bptr[ps]);
    }

    float acc[2][8][4];
#pragma unroll
    for (int mt = 0; mt < 2; mt++)
#pragma unroll
        for (int nt = 0; nt < 8; nt++)
#pragma unroll
            for (int j = 0; j < 4; j++) acc[mt][nt][j] = 0.f;

    const int NC = K >> 5;
    for (int i = 0; i < NC; i++) {
        float* As = Ab[i & 1];
        float* Bs = Bb[i & 1];
#pragma unroll
        for (int ps = 0; ps < 4; ps++) {
            uint32_t* pa = (uint32_t*)(As + stOff[ps]);
            pa[0] = to_tf32_bits(aR[ps].x);
            pa[1] = to_tf32_bits(aR[ps].y);
            pa[2] = to_tf32_bits(aR[ps].z);
            pa[3] = to_tf32_bits(aR[ps].w);
            uint32_t* pb = (uint32_t*)(Bs + stOff[ps]);
            pb[0] = to_tf32_bits(bR[ps].x);
            pb[1] = to_tf32_bits(bR[ps].y);
            pb[2] = to_tf32_bits(bR[ps].z);
            pb[3] = to_tf32_bits(bR[ps].w);
        }
        __syncthreads();

        if (i + 1 < NC) {
            const int co = (i + 1) * 32;
#pragma unroll
            for (int ps = 0; ps < 4; ps++) {
                aR[ps] = *(const float4*)(Aptr[ps] + co);
                bR[ps] = *(const float4*)(Bptr[ps] + co);
            }
        }

        const uint32_t* Au = (const uint32_t*)As;
        const uint32_t* Bu = (const uint32_t*)Bs;
#pragma unroll
        for (int kk = 0; kk < 4; kk++) {
            const int s0 = 4 * (((kk * 2)    ) ^ gid);
            const int s1 = 4 * (((kk * 2) + 1) ^ gid);
            uint32_t af[2][4];
#pragma unroll
            for (int mt = 0; mt < 2; mt++) {
                int rA = wm * 32 + mt * 16 + gid;
                af[mt][0] = Au[rA * 32 + tig + s0];
                af[mt][1] = Au[(rA + 8) * 32 + tig + s0];
                af[mt][2] = Au[rA * 32 + tig + s1];
                af[mt][3] = Au[(rA + 8) * 32 + tig + s1];
            }
            uint32_t bf[8][2];
#pragma unroll
            for (int nt = 0; nt < 8; nt++) {
                int rB = wn * 64 + nt * 8 + gid;
                bf[nt][0] = Bu[rB * 32 + tig + s0];
                bf[nt][1] = Bu[rB * 32 + tig + s1];
            }
#pragma unroll
            for (int mt = 0; mt < 2; mt++)
#pragma unroll
                for (int nt = 0; nt < 8; nt++)
                    mma_tf32(acc[mt][nt], af[mt][0], af[mt][1], af[mt][2],
                             af[mt][3], bf[nt][0], bf[nt][1]);
        }
        __syncthreads();
    }

    // epilogue: direct stores (32B segments per 4-lane group = full sectors)
#pragma unroll
    for (int mt = 0; mt < 2; mt++) {
        int row = row0 + wm * 32 + mt * 16 + gid;
        if (row >= M) continue;
#pragma unroll
        for (int nt = 0; nt < 8; nt++) {
            int col = col0 + wn * 64 + nt * 8 + tig * 2;
            if (col >= N) continue;
            float b0v = bias ? bias[col] : 0.f;
            float* p0 = C + (size_t)row * ldc + col;
            float* p1 = C + (size_t)(row + 8) * ldc + col;
            if (col + 1 < N) {
                float b1v = bias ? bias[col + 1] : 0.f;
                *(float2*)p0 = make_float2(acc[mt][nt][0] + b0v,
                                           acc[mt][nt][1] + b1v);
                if (row + 8 < M)
                    *(float2*)p1 = make_float2(acc[mt][nt][2] + b0v,
                                               acc[mt][nt][3] + b1v);
            } else {
                p0[0] = acc[mt][nt][0] + b0v;
                if (row + 8 < M) p1[0] = acc[mt][nt][2] + b0v;
            }
        }
    }
}

// ---------------------------------------------------------------------------
// fp32 SGEMM (small hb2 GEMM only)
// ---------------------------------------------------------------------------
__global__ void __launch_bounds__(256)
sgemm_nt(const float* __restrict__ A, int lda,
         const float* __restrict__ Bw, int ldb,
         const float* __restrict__ bias,
         float* __restrict__ C, int ldc,
         const int* __restrict__ tok,
         int M, int N, int K)
{
    __shared__ __align__(16) float As[8][132];
    __shared__ __align__(16) float Bs[8][128];

    const int tid  = threadIdx.x;
    const int row0 = blockIdx.y * 128;
    const int col0 = blockIdx.x * 128;

    const int li = tid >> 1;
    const int lk = (tid & 1) * 4;

    int ar = row0 + li;
    if (ar >= M) ar = M - 1;
    if (tok) ar = tok[ar];
    const float* Ap = A + (size_t)ar * lda + lk;

    int brn = col0 + li;
    const bool bval = (brn < N);
    const float* Bp = Bw + (size_t)(bval ? brn : 0) * ldb + lk;

    const int ty = tid >> 4;
    const int tx = tid & 15;

    unsigned long long acc2[8][4];
#pragma unroll
    for (int r = 0; r < 8; r++)
#pragma unroll
        for (int c = 0; c < 4; c++) acc2[r][c] = 0ull;

    for (int k0 = 0; k0 < K; k0 += 8) {
        float4 av = *(const float4*)(Ap + k0);
        float4 bv = bval ? *(const float4*)(Bp + k0) : make_float4(0.f, 0.f, 0.f, 0.f);

        __syncthreads();
        As[lk + 0][li] = av.x; As[lk + 1][li] = av.y;
        As[lk + 2][li] = av.z; As[lk + 3][li] = av.w;
        Bs[lk + 0][li] = bv.x; Bs[lk + 1][li] = bv.y;
        Bs[lk + 2][li] = bv.z; Bs[lk + 3][li] = bv.w;
        __syncthreads();

#pragma unroll
        for (int kk = 0; kk < 8; kk++) {
            float4 a0 = *(const float4*)&As[kk][ty * 8];
            float4 a1 = *(const float4*)&As[kk][ty * 8 + 4];
            const unsigned long long* bp = (const unsigned long long*)&Bs[kk][tx * 8];
            unsigned long long b0 = bp[0], b1 = bp[1], b2 = bp[2], b3 = bp[3];
            float arr[8] = {a0.x, a0.y, a0.z, a0.w, a1.x, a1.y, a1.z, a1.w};
#pragma unroll
            for (int r = 0; r < 8; r++) {
                unsigned long long ad = f2pack(arr[r], arr[r]);
                ffma2(acc2[r][0], ad, b0);
                ffma2(acc2[r][1], ad, b1);
                ffma2(acc2[r][2], ad, b2);
                ffma2(acc2[r][3], ad, b3);
            }
        }
    }

    const bool fullcol = (col0 + 128 <= N);
#pragma unroll
    for (int r = 0; r < 8; r++) {
        int row = row0 + ty * 8 + r;
        if (row >= M) continue;
        float* Cp = C + (size_t)row * ldc + col0 + tx * 8;
        float v[8];
#pragma unroll
        for (int c = 0; c < 4; c++) f2unpack(acc2[r][c], v[2 * c], v[2 * c + 1]);
        if (fullcol) {
            if (bias) {
#pragma unroll
                for (int c = 0; c < 8; c++) v[c] += bias[col0 + tx * 8 + c];
            }
            *(float4*)(Cp)     = make_float4(v[0], v[1], v[2], v[3]);
            *(float4*)(Cp + 4) = make_float4(v[4], v[5], v[6], v[7]);
        } else {
#pragma unroll
            for (int c = 0; c < 8; c++) {
                int col = col0 + tx * 8 + c;
                if (col < N) Cp[c] = v[c] + (bias ? bias[col] : 0.f);
            }
        }
    }
}

// ---------------------------------------------------------------------------
// GRU scan: column-partitioned persistent kernel, release/acquire chip
// barrier, double-buffered h broadcast.
// ---------------------------------------------------------------------------
#define SMEM_W   0
#define SMEM_HS  12288
#define SMEM_SG  77824
#define SMEM_SCAN 80896

__global__ void __launch_bounds__(SCAN_THREADS)
gru_scan2(const float* __restrict__ xg,
          const float* __restrict__ hb,
          const float* __restrict__ WT,
          const float* __restrict__ bhh,
          float* __restrict__ hfin,
          float* __restrict__ preds,
          float* __restrict__ tail,
          float* __restrict__ hsg,      // [2][128][64] float2
          int*   __restrict__ cnt)
{
    float4* w_s = (float4*)(dsmem + SMEM_W);
    float2* hs2 = (float2*)(dsmem + SMEM_HS);
    float4* sg  = (float4*)(dsmem + SMEM_SG);

    const int tid = threadIdx.x;
    const int q   = tid >> 6;
    const int b   = tid & 63;
    const int c0  = blockIdx.x * 4;
    const int kk0 = c0 >> 1;

    for (int i = tid; i < 768; i += SCAN_THREADS) {
        int k = i / 3, g = i - 3 * k;
        w_s[k * 3 + g] = *(const float4*)(WT + (size_t)k * G3 + g * NHID + c0);
    }
    for (int i = tid; i < 4096; i += SCAN_THREADS)
        ((float4*)hs2)[i] = make_float4(0.f, 0.f, 0.f, 0.f);

    const float4 bh4 = *(const float4*)(bhh + q * NHID + c0);
    const unsigned long long bhA = f2pack(bh4.x, bh4.y);
    const unsigned long long bhB = f2pack(bh4.z, bh4.w);

    float4 hbr = make_float4(0.f, 0.f, 0.f, 0.f), hbz = hbr, hbn = hbr;
    if (hb && tid < 64) {
        const float* hp = hb + (size_t)b * G3;
        hbr = *(const float4*)(hp + c0);
        hbz = *(const float4*)(hp + NHID + c0);
        hbn = *(const float4*)(hp + 2 * NHID + c0);
    }
    __syncthreads();

    for (int t = 0; t < TT; t++) {
        const int slot = t & 1;
        float2* hsg2 = (float2*)hsg + slot * 8192;

        float4 xr, xz, xn;
        if (tid < 64) {
            const float* xp = xg + (size_t)(t * BB + b) * G3;
            xr = *(const float4*)(xp + c0);
            xz = *(const float4*)(xp + NHID + c0);
            xn = *(const float4*)(xp + 2 * NHID + c0);
        }

        unsigned long long accA = bhA, accB = bhB;
#pragma unroll 8
        for (int kk = 0; kk < 128; kk++) {
            ulonglong2 w0 = *(const ulonglong2*)&w_s[(2 * kk)     * 3 + q];
            ulonglong2 w1 = *(const ulonglong2*)&w_s[(2 * kk + 1) * 3 + q];
            float2 h2 = hs2[kk * 64 + b];
            unsigned long long h0 = f2pack(h2.x, h2.x);
            unsigned long long h1 = f2pack(h2.y, h2.y);
            ffma2(accA, w0.x, h0);
            ffma2(accB, w0.y, h0);
            ffma2(accA, w1.x, h1);
            ffma2(accB, w1.y, h1);
        }
        float4 accv;
        f2unpack(accA, accv.x, accv.y);
        f2unpack(accB, accv.z, accv.w);
        sg[q * 64 + b] = accv;
        __syncthreads();

        if (tid < 64) {
            float4 rr4 = sg[b];
            float4 zz4 = sg[64 + b];
            float4 nn4 = sg[128 + b];
            float2 ho01 = hs2[kk0 * 64 + b];
            float2 ho23 = hs2[(kk0 + 1) * 64 + b];
            const float* rr = (const float*)&rr4;
            const float* zz = (const float*)&zz4;
            const float* nn = (const float*)&nn4;
            const float* xrv = (const float*)&xr;
            const float* xzv = (const float*)&xz;
            const float* xnv = (const float*)&xn;
            const float* hrv = (const float*)&hbr;
            const float* hzv = (const float*)&hbz;
            const float* hnv = (const float*)&hbn;
            float ho[4] = {ho01.x, ho01.y, ho23.x, ho23.y};
            float hn[4];
#pragma unroll
            for (int j = 0; j < 4; j++) {
                float r = 1.f / (1.f + __expf(-(xrv[j] + hrv[j] + rr[j])));
                float z = 1.f / (1.f + __expf(-(xzv[j] + hzv[j] + zz[j])));
                float n = tanhf(xnv[j] + hnv[j] + r * nn[j]);
                hn[j] = (1.f - z) * n + z * ho[j];
            }
            if (preds)
                *(float4*)(preds + (size_t)(t * BB + b) * NHID + c0) =
                    make_float4(hn[0], hn[1], hn[2], hn[3]);
            if (t == TT - 1) {
                if (hfin)
                    *(float4*)(hfin + (size_t)b * NHID + c0) =
                        make_float4(hn[0], hn[1], hn[2], hn[3]);
                if (tail)
                    *(float4*)(tail + (size_t)b * NHID + c0) =
                        make_float4(hn[0], hn[1], hn[2], hn[3]);
            } else {
                hsg2[kk0 * 64 + b]       = make_float2(hn[0], hn[1]);
                hsg2[(kk0 + 1) * 64 + b] = make_float2(hn[2], hn[3]);
            }
        }
        if (t == TT - 1) break;

        __syncthreads();
        if (tid == 0) {
            asm volatile("red.release.gpu.global.add.s32 [%0], 1;"
                         :: "l"(cnt + t) : "memory");
            int v;
            do {
                asm volatile("ld.acquire.gpu.global.s32 %0, [%1];"
                             : "=r"(v) : "l"(cnt + t) : "memory");
            } while (v < SCAN_CTAS);
        }
        __syncthreads();

        {
            const float4* src = (const float4*)((const float2*)hsg + slot * 8192);
            float4* dst = (float4*)hs2;
            for (int i = tid; i < 4096; i += SCAN_THREADS)
                dst[i] = __ldcg(src + i);
        }
        __syncthreads();
    }
}

// ---------------------------------------------------------------------------
// Launcher
// ---------------------------------------------------------------------------
extern "C" void kernel_launch(void* const* d_in, const int* in_sizes, int n_in,
                              void* d_out, int out_size)
{
    const int*   tokens = (const int*)  d_in[0];
    const float* E      = (const float*)d_in[1];
    const float* Wih1   = (const float*)d_in[2];
    const float* Whh1   = (const float*)d_in[3];
    const float* bih1   = (const float*)d_in[4];
    const float* bhh1   = (const float*)d_in[5];
    const float* Wih2   = (const float*)d_in[6];
    const float* Whh2   = (const float*)d_in[7];
    const float* bih2   = (const float*)d_in[8];
    const float* bhh2   = (const float*)d_in[9];
    // d_in[10..14] dead (attention context == h1 exactly)
    const float* Wd     = (const float*)d_in[15];
    const float* bd     = (const float*)d_in[16];
    float* out = (float*)d_out;

    float *xg1, *xg2, *hb2, *h1, *preds, *WT1, *WT2, *hsg;
    int *cnt1, *cnt2;
    cudaGetSymbolAddress((void**)&xg1,   g_xg1);
    cudaGetSymbolAddress((void**)&xg2,   g_xg2);
    cudaGetSymbolAddress((void**)&hb2,   g_hb2);
    cudaGetSymbolAddress((void**)&h1,    g_h1);
    cudaGetSymbolAddress((void**)&preds, g_preds);
    cudaGetSymbolAddress((void**)&WT1,   g_WT1);
    cudaGetSymbolAddress((void**)&WT2,   g_WT2);
    cudaGetSymbolAddress((void**)&hsg,   g_hsg);
    cudaGetSymbolAddress((void**)&cnt1,  g_cnt1);
    cudaGetSymbolAddress((void**)&cnt2,  g_cnt2);

    cudaFuncSetAttribute(gru_scan2, cudaFuncAttributeMaxDynamicSharedMemorySize,
                         SMEM_SCAN);
    cudaFuncSetAttribute(gemm_mma, cudaFuncAttributeMaxDynamicSharedMemorySize,
                         GM_SMEM);

    float* tail = nullptr;
    if (out_size >= MM * NVOC + BB * NHID) tail = out + (size_t)MM * NVOC;

    init_cnt<<<1, 256>>>();

    transpose_k<<<dim3(24, 8), dim3(32, 8)>>>(Whh1, WT1);
    transpose_k<<<dim3(24, 8), dim3(32, 8)>>>(Whh2, WT2);

    // input-gate GEMMs (tf32 mma.sync, embedding gather fused)
    gemm_mma<<<dim3(6, 64), GM_THREADS, GM_SMEM>>>(
        E, NIN, Wih1, NIN, bih1, xg1, G3, tokens, MM, G3, NIN);
    gemm_mma<<<dim3(6, 64), GM_THREADS, GM_SMEM>>>(
        E, NIN, Wih2 + NHID, NHID + NIN, nullptr, xg2, G3, tokens, MM, G3, NIN);

    // GRU1 scan -> h1 (+ hidden-state output tail)
    gru_scan2<<<SCAN_CTAS, SCAN_THREADS, SMEM_SCAN>>>(
        xg1, nullptr, WT1, bhh1, h1, nullptr, tail, hsg, cnt1);

    // constant GRU2 gate part
    sgemm_nt<<<dim3(6, 1), 256>>>(h1, NHID, Wih2, NHID + NIN, bih2,
                                  hb2, G3, nullptr, BB, G3, NHID);

    // GRU2 scan -> preds
    gru_scan2<<<SCAN_CTAS, SCAN_THREADS, SMEM_SCAN>>>(
        xg2, hb2, WT2, bhh2, nullptr, preds, nullptr, hsg, cnt2);

    // decoder (tf32 mma.sync)
    gemm_mma<<<dim3(79, 64), GM_THREADS, GM_SMEM>>>(
        preds, NHID, Wd, NHID, bd, out, NVOC, nullptr, MM, NVOC, NHID);
}

// round 6
// speedup vs baseline: 3.2639x; 1.2855x over previous
#include <cuda_runtime.h>
#include <cuda_bf16.h>
#include <cstdint>

// ---------------------------------------------------------------------------
// Problem constants
// ---------------------------------------------------------------------------
#define NVOC 10000
#define NIN  1024
#define NHID 256
#define G3   768
#define TT   128
#define BB   64
#define MM   (TT*BB)

#define CL 8
#define SCAN_THREADS 192

extern __shared__ char dsmem[];

// ---------------------------------------------------------------------------
// Device scratch
// ---------------------------------------------------------------------------
__device__ float g_xg1  [MM * G3];
__device__ float g_xg2  [MM * G3];
__device__ float g_hb2  [BB * G3];
__device__ float g_h1   [BB * NHID];
__device__ float g_preds[MM * NHID];
__device__ float g_WT1  [NHID * G3];
__device__ float g_WT2  [NHID * G3];

// ---------------------------------------------------------------------------
// Helpers
// ---------------------------------------------------------------------------
__device__ __forceinline__ uint32_t smem_u32(const void* p) {
    uint32_t a;
    asm("{ .reg .u64 t; cvta.to.shared.u64 t, %1; cvt.u32.u64 %0, t; }"
        : "=r"(a) : "l"(p));
    return a;
}
__device__ __forceinline__ uint32_t to_tf32_bits(float x) {
    float y;
    asm("cvt.rna.tf32.f32 %0, %1;" : "=f"(y) : "f"(x));
    return __float_as_uint(y);
}
__device__ __forceinline__ unsigned long long f2pack(float lo, float hi) {
    unsigned long long v;
    asm("mov.b64 %0, {%1, %2};" : "=l"(v) : "f"(lo), "f"(hi));
    return v;
}
__device__ __forceinline__ void f2unpack(unsigned long long v, float& lo, float& hi) {
    asm("mov.b64 {%0, %1}, %2;" : "=f"(lo), "=f"(hi) : "l"(v));
}
__device__ __forceinline__ void ffma2(unsigned long long& d, unsigned long long a,
                                      unsigned long long b) {
    asm("fma.rn.f32x2 %0, %1, %2, %3;" : "=l"(d) : "l"(a), "l"(b), "l"(d));
}
__device__ __forceinline__ void mma_tf32(float* d, uint32_t a0, uint32_t a1,
                                         uint32_t a2, uint32_t a3,
                                         uint32_t b0, uint32_t b1) {
    asm volatile(
        "mma.sync.aligned.m16n8k8.row.col.f32.tf32.tf32.f32 "
        "{%0,%1,%2,%3}, {%4,%5,%6,%7}, {%8,%9}, {%0,%1,%2,%3};"
        : "+f"(d[0]), "+f"(d[1]), "+f"(d[2]), "+f"(d[3])
        : "r"(a0), "r"(a1), "r"(a2), "r"(a3), "r"(b0), "r"(b1));
}
__device__ __forceinline__ uint32_t my_ctarank() {
    uint32_t r;
    asm("mov.u32 %0, %%cluster_ctarank;" : "=r"(r));
    return r;
}
__device__ __forceinline__ void dsmem_bcast(uint32_t laddr, float v) {
    uint32_t bits = __float_as_uint(v);
#pragma unroll
    for (int p = 0; p < CL; p++) {
        uint32_t ra;
        asm volatile("mapa.shared::cluster.u32 %0, %1, %2;"
                     : "=r"(ra) : "r"(laddr), "r"(p));
        asm volatile("st.shared::cluster.b32 [%0], %1;"
                     :: "r"(ra), "r"(bits) : "memory");
    }
}

// ---------------------------------------------------------------------------
__global__ void transpose_k(const float* __restrict__ in, float* __restrict__ out) {
    __shared__ float tile[32][33];
    int r0 = blockIdx.x * 32;
    int c0 = blockIdx.y * 32;
    for (int i = threadIdx.y; i < 32; i += 8)
        tile[i][threadIdx.x] = in[(r0 + i) * NHID + (c0 + threadIdx.x)];
    __syncthreads();
    for (int i = threadIdx.y; i < 32; i += 8)
        out[(c0 + i) * G3 + (r0 + threadIdx.x)] = tile[threadIdx.x][i];
}

// ---------------------------------------------------------------------------
// tf32 mma.sync GEMM (R5 passing version, unchanged)
// ---------------------------------------------------------------------------
#define GM_THREADS 256
#define GM_SMEM    65536

__global__ void __launch_bounds__(GM_THREADS, 1)
gemm_mma(const float* __restrict__ A, int lda,
         const float* __restrict__ Bw, int ldb,
         const float* __restrict__ bias,
         float* __restrict__ C, int ldc,
         const int* __restrict__ tok,
         int M, int N, int K)
{
    float* smem = (float*)dsmem;
    float* Ab[2] = {smem,         smem + 4096};
    float* Bb[2] = {smem + 8192,  smem + 12288};

    const int tid  = threadIdx.x;
    const int wid  = tid >> 5, lane = tid & 31;
    const int wm   = wid >> 1;
    const int wn   = wid & 1;
    const int gid  = lane >> 2;
    const int tig  = lane & 3;
    const int row0 = blockIdx.y * 128, col0 = blockIdx.x * 128;

    const int sr = tid >> 3;
    const int sc = (tid & 7) * 4;
    const float* Aptr[4];
    const float* Bptr[4];
#pragma unroll
    for (int ps = 0; ps < 4; ps++) {
        int ar = row0 + sr + ps * 32;
        if (ar >= M) ar = M - 1;
        if (tok) ar = tok[ar];
        Aptr[ps] = A + (size_t)ar * lda + sc;
        int br = col0 + sr + ps * 32;
        if (br >= N) br = N - 1;
        Bptr[ps] = Bw + (size_t)br * ldb + sc;
    }
    uint32_t stOff[4];
#pragma unroll
    for (int ps = 0; ps < 4; ps++) {
        int r = sr + ps * 32;
        stOff[ps] = r * 32 + 4 * ((sc >> 2) ^ (r & 7));
    }

    float4 aR[4], bR[4];
#pragma unroll
    for (int ps = 0; ps < 4; ps++) {
        aR[ps] = *(const float4*)(Aptr[ps]);
        bR[ps] = *(const float4*)(Bptr[ps]);
    }

    float acc[2][8][4];
#pragma unroll
    for (int mt = 0; mt < 2; mt++)
#pragma unroll
        for (int nt = 0; nt < 8; nt++)
#pragma unroll
            for (int j = 0; j < 4; j++) acc[mt][nt][j] = 0.f;

    const int NC = K >> 5;
    for (int i = 0; i < NC; i++) {
        float* As = Ab[i & 1];
        float* Bs = Bb[i & 1];
#pragma unroll
        for (int ps = 0; ps < 4; ps++) {
            uint32_t* pa = (uint32_t*)(As + stOff[ps]);
            pa[0] = to_tf32_bits(aR[ps].x);
            pa[1] = to_tf32_bits(aR[ps].y);
            pa[2] = to_tf32_bits(aR[ps].z);
            pa[3] = to_tf32_bits(aR[ps].w);
            uint32_t* pb = (uint32_t*)(Bs + stOff[ps]);
            pb[0] = to_tf32_bits(bR[ps].x);
            pb[1] = to_tf32_bits(bR[ps].y);
            pb[2] = to_tf32_bits(bR[ps].z);
            pb[3] = to_tf32_bits(bR[ps].w);
        }
        __syncthreads();

        if (i + 1 < NC) {
            const int co = (i + 1) * 32;
#pragma unroll
            for (int ps = 0; ps < 4; ps++) {
                aR[ps] = *(const float4*)(Aptr[ps] + co);
                bR[ps] = *(const float4*)(Bptr[ps] + co);
            }
        }

        const uint32_t* Au = (const uint32_t*)As;
        const uint32_t* Bu = (const uint32_t*)Bs;
#pragma unroll
        for (int kk = 0; kk < 4; kk++) {
            const int s0 = 4 * (((kk * 2)    ) ^ gid);
            const int s1 = 4 * (((kk * 2) + 1) ^ gid);
            uint32_t af[2][4];
#pragma unroll
            for (int mt = 0; mt < 2; mt++) {
                int rA = wm * 32 + mt * 16 + gid;
                af[mt][0] = Au[rA * 32 + tig + s0];
                af[mt][1] = Au[(rA + 8) * 32 + tig + s0];
                af[mt][2] = Au[rA * 32 + tig + s1];
                af[mt][3] = Au[(rA + 8) * 32 + tig + s1];
            }
            uint32_t bf[8][2];
#pragma unroll
            for (int nt = 0; nt < 8; nt++) {
                int rB = wn * 64 + nt * 8 + gid;
                bf[nt][0] = Bu[rB * 32 + tig + s0];
                bf[nt][1] = Bu[rB * 32 + tig + s1];
            }
#pragma unroll
            for (int mt = 0; mt < 2; mt++)
#pragma unroll
                for (int nt = 0; nt < 8; nt++)
                    mma_tf32(acc[mt][nt], af[mt][0], af[mt][1], af[mt][2],
                             af[mt][3], bf[nt][0], bf[nt][1]);
        }
        __syncthreads();
    }

#pragma unroll
    for (int mt = 0; mt < 2; mt++) {
        int row = row0 + wm * 32 + mt * 16 + gid;
        if (row >= M) continue;
#pragma unroll
        for (int nt = 0; nt < 8; nt++) {
            int col = col0 + wn * 64 + nt * 8 + tig * 2;
            if (col >= N) continue;
            float b0v = bias ? bias[col] : 0.f;
            float* p0 = C + (size_t)row * ldc + col;
            float* p1 = C + (size_t)(row + 8) * ldc + col;
            if (col + 1 < N) {
                float b1v = bias ? bias[col + 1] : 0.f;
                *(float2*)p0 = make_float2(acc[mt][nt][0] + b0v,
                                           acc[mt][nt][1] + b1v);
                if (row + 8 < M)
                    *(float2*)p1 = make_float2(acc[mt][nt][2] + b0v,
                                               acc[mt][nt][3] + b1v);
            } else {
                p0[0] = acc[mt][nt][0] + b0v;
                if (row + 8 < M) p1[0] = acc[mt][nt][2] + b0v;
            }
        }
    }
}

// ---------------------------------------------------------------------------
// fp32 SGEMM (small hb2 GEMM only)
// ---------------------------------------------------------------------------
__global__ void __launch_bounds__(256)
sgemm_nt(const float* __restrict__ A, int lda,
         const float* __restrict__ Bw, int ldb,
         const float* __restrict__ bias,
         float* __restrict__ C, int ldc,
         int M, int N, int K)
{
    __shared__ __align__(16) float As[8][132];
    __shared__ __align__(16) float Bs[8][128];

    const int tid  = threadIdx.x;
    const int row0 = blockIdx.y * 128;
    const int col0 = blockIdx.x * 128;

    const int li = tid >> 1;
    const int lk = (tid & 1) * 4;

    int ar = row0 + li;
    if (ar >= M) ar = M - 1;
    const float* Ap = A + (size_t)ar * lda + lk;

    int brn = col0 + li;
    const bool bval = (brn < N);
    const float* Bp = Bw + (size_t)(bval ? brn : 0) * ldb + lk;

    const int ty = tid >> 4;
    const int tx = tid & 15;

    unsigned long long acc2[8][4];
#pragma unroll
    for (int r = 0; r < 8; r++)
#pragma unroll
        for (int c = 0; c < 4; c++) acc2[r][c] = 0ull;

    for (int k0 = 0; k0 < K; k0 += 8) {
        float4 av = *(const float4*)(Ap + k0);
        float4 bv = bval ? *(const float4*)(Bp + k0) : make_float4(0.f, 0.f, 0.f, 0.f);

        __syncthreads();
        As[lk + 0][li] = av.x; As[lk + 1][li] = av.y;
        As[lk + 2][li] = av.z; As[lk + 3][li] = av.w;
        Bs[lk + 0][li] = bv.x; Bs[lk + 1][li] = bv.y;
        Bs[lk + 2][li] = bv.z; Bs[lk + 3][li] = bv.w;
        __syncthreads();

#pragma unroll
        for (int kk = 0; kk < 8; kk++) {
            float4 a0 = *(const float4*)&As[kk][ty * 8];
            float4 a1 = *(const float4*)&As[kk][ty * 8 + 4];
            const unsigned long long* bp = (const unsigned long long*)&Bs[kk][tx * 8];
            unsigned long long b0 = bp[0], b1 = bp[1], b2 = bp[2], b3 = bp[3];
            float arr[8] = {a0.x, a0.y, a0.z, a0.w, a1.x, a1.y, a1.z, a1.w};
#pragma unroll
            for (int r = 0; r < 8; r++) {
                unsigned long long ad = f2pack(arr[r], arr[r]);
                ffma2(acc2[r][0], ad, b0);
                ffma2(acc2[r][1], ad, b1);
                ffma2(acc2[r][2], ad, b2);
                ffma2(acc2[r][3], ad, b3);
            }
        }
    }

    const bool fullcol = (col0 + 128 <= N);
#pragma unroll
    for (int r = 0; r < 8; r++) {
        int row = row0 + ty * 8 + r;
        if (row >= M) continue;
        float* Cp = C + (size_t)row * ldc + col0 + tx * 8;
        float v[8];
#pragma unroll
        for (int c = 0; c < 4; c++) f2unpack(acc2[r][c], v[2 * c], v[2 * c + 1]);
        if (fullcol) {
            if (bias) {
#pragma unroll
                for (int c = 0; c < 8; c++) v[c] += bias[col0 + tx * 8 + c];
            }
            *(float4*)(Cp)     = make_float4(v[0], v[1], v[2], v[3]);
            *(float4*)(Cp + 4) = make_float4(v[4], v[5], v[6], v[7]);
        } else {
#pragma unroll
            for (int c = 0; c < 8; c++) {
                int col = col0 + tx * 8 + c;
                if (col < N) Cp[c] = v[c] + (bias ? bias[col] : 0.f);
            }
        }
    }
}

// ---------------------------------------------------------------------------
// GRU scan v3: 8 clusters x 8 CTAs; cluster owns 8 batch lanes (independent
// recurrence). CTA rank owns hidden cols [32r,32r+32): 96KB W slice resident
// in smem; h double-buffered; per-step DSMEM broadcast + cluster.sync.
// ---------------------------------------------------------------------------
#define SC_W   0
#define SC_H   98304
#define SC_SG  114944
#define SC_XS  118016
#define SC_XB  124160
#define SC_SMEM 127232
#define HBUF   2080

__global__ void __launch_bounds__(SCAN_THREADS) __cluster_dims__(CL, 1, 1)
gru_cluster(const float* __restrict__ xg,
            const float* __restrict__ hb,
            const float* __restrict__ WT,
            const float* __restrict__ bhh,
            float* __restrict__ hfin,
            float* __restrict__ preds,
            float* __restrict__ tail)
{
    float4* w_s  = (float4*)(dsmem + SC_W);
    float*  hbuf = (float*) (dsmem + SC_H);
    float4* sg4  = (float4*)(dsmem + SC_SG);
    float*  sgf  = (float*) (dsmem + SC_SG);
    float*  xs   = (float*) (dsmem + SC_XS);
    float*  xb   = (float*) (dsmem + SC_XB);

    const int tid  = threadIdx.x;
    const int rank = (int)my_ctarank();
    const int cid  = blockIdx.x >> 3;
    const int b0   = cid * 8;
    const int colbase = rank * 32;

    for (int i = tid; i < 256 * 24; i += SCAN_THREADS) {
        int k = i / 24, j = i - 24 * k;
        int g = j >> 3, quad = j & 7;
        w_s[i] = *(const float4*)(WT + (size_t)k * G3 + g * NHID + colbase + quad * 4);
    }
    for (int i = tid; i < 2 * HBUF; i += SCAN_THREADS) hbuf[i] = 0.f;
    for (int i = tid; i < 768; i += SCAN_THREADS) {
        int b = i / 96, j = i - 96 * b;
        int g = j >> 5, c = j & 31;
        xb[i] = hb ? hb[(size_t)(b0 + b) * G3 + g * NHID + colbase + c] : 0.f;
    }

    const int gb   = tid & 7;
    const int quad = (tid >> 3) & 7;
    const int q    = tid >> 6;
    const float4 bh4 = *(const float4*)(bhh + q * NHID + colbase + quad * 4);
    const unsigned long long bhA = f2pack(bh4.x, bh4.y);
    const unsigned long long bhB = f2pack(bh4.z, bh4.w);

    const int pb = tid / 24;
    const int pj = tid - 24 * pb;
    const int pg = pj >> 3, pf = pj & 7;
    const float* xgp = xg + (size_t)(b0 + pb) * G3 + pg * NHID + colbase + pf * 4;
    float* xss = xs + pb * 96 + pg * 32 + pf * 4;

    __syncthreads();
    asm volatile("barrier.cluster.arrive.aligned;" ::: "memory");
    asm volatile("barrier.cluster.wait.aligned;"   ::: "memory");

    float4 v = *(const float4*)(xgp);

    for (int t = 0; t < TT; t++) {
        const int cur = t & 1;

        *(float4*)(xss + cur * 768) = v;
        if (t + 1 < TT) v = *(const float4*)(xgp + (size_t)(t + 1) * BB * G3);

        const float* hc = hbuf + cur * HBUF;
        unsigned long long accA = bhA, accB = bhB;
        const float4* wp = w_s + q * 8 + quad;
#pragma unroll 16
        for (int kk = 0; kk < 128; kk++) {
            ulonglong2 w0 = *(const ulonglong2*)(wp + (2 * kk)     * 24);
            ulonglong2 w1 = *(const ulonglong2*)(wp + (2 * kk + 1) * 24);
            float2 h2 = *(const float2*)(hc + gb * 260 + 2 * kk);
            unsigned long long h0 = f2pack(h2.x, h2.x);
            unsigned long long h1 = f2pack(h2.y, h2.y);
            ffma2(accA, w0.x, h0);
            ffma2(accB, w0.y, h0);
            ffma2(accA, w1.x, h1);
            ffma2(accB, w1.y, h1);
        }
        float4 accv;
        f2unpack(accA, accv.x, accv.y);
        f2unpack(accB, accv.z, accv.w);
        sg4[q * 64 + gb * 8 + quad] = accv;
        __syncthreads();

        for (int idx = tid; idx < 256; idx += SCAN_THREADS) {
            int tb = idx >> 5;
            int c  = idx & 31;
            const float* xr  = xs + cur * 768 + tb * 96;
            const float* xbr = xb + tb * 96;
            float gr = xr[c]      + xbr[c];
            float gz = xr[32 + c] + xbr[32 + c];
            float gn = xr[64 + c] + xbr[64 + c];
            float hgr = sgf[      tb * 32 + c];
            float hgz = sgf[256 + tb * 32 + c];
            float hgn = sgf[512 + tb * 32 + c];
            float ho  = hc[tb * 260 + colbase + c];
            float r = 1.f / (1.f + __expf(-(gr + hgr)));
            float z = 1.f / (1.f + __expf(-(gz + hgz)));
            float n = tanhf(gn + r * hgn);
            float hn = (1.f - z) * n + z * ho;
            if (preds)
                preds[(size_t)(t * BB + b0 + tb) * NHID + colbase + c] = hn;
            if (t == TT - 1) {
                if (hfin) hfin[(size_t)(b0 + tb) * NHID + colbase + c] = hn;
                if (tail) tail[(size_t)(b0 + tb) * NHID + colbase + c] = hn;
            } else {
                uint32_t laddr = smem_u32(
                    hbuf + (1 - cur) * HBUF + tb * 260 + colbase + c);
                dsmem_bcast(laddr, hn);
            }
        }

        if (t == TT - 1) break;
        asm volatile("barrier.cluster.arrive.aligned;" ::: "memory");
        asm volatile("barrier.cluster.wait.aligned;"   ::: "memory");
    }
}

// ---------------------------------------------------------------------------
// Launcher
// ---------------------------------------------------------------------------
extern "C" void kernel_launch(void* const* d_in, const int* in_sizes, int n_in,
                              void* d_out, int out_size)
{
    const int*   tokens = (const int*)  d_in[0];
    const float* E      = (const float*)d_in[1];
    const float* Wih1   = (const float*)d_in[2];
    const float* Whh1   = (const float*)d_in[3];
    const float* bih1   = (const float*)d_in[4];
    const float* bhh1   = (const float*)d_in[5];
    const float* Wih2   = (const float*)d_in[6];
    const float* Whh2   = (const float*)d_in[7];
    const float* bih2   = (const float*)d_in[8];
    const float* bhh2   = (const float*)d_in[9];
    // d_in[10..14] dead (attention context == h1 exactly)
    const float* Wd     = (const float*)d_in[15];
    const float* bd     = (const float*)d_in[16];
    float* out = (float*)d_out;

    float *xg1, *xg2, *hb2, *h1, *preds, *WT1, *WT2;
    cudaGetSymbolAddress((void**)&xg1,   g_xg1);
    cudaGetSymbolAddress((void**)&xg2,   g_xg2);
    cudaGetSymbolAddress((void**)&hb2,   g_hb2);
    cudaGetSymbolAddress((void**)&h1,    g_h1);
    cudaGetSymbolAddress((void**)&preds, g_preds);
    cudaGetSymbolAddress((void**)&WT1,   g_WT1);
    cudaGetSymbolAddress((void**)&WT2,   g_WT2);

    cudaFuncSetAttribute(gru_cluster, cudaFuncAttributeMaxDynamicSharedMemorySize,
                         SC_SMEM);
    cudaFuncSetAttribute(gemm_mma, cudaFuncAttributeMaxDynamicSharedMemorySize,
                         GM_SMEM);

    float* tail = nullptr;
    if (out_size >= MM * NVOC + BB * NHID) tail = out + (size_t)MM * NVOC;

    transpose_k<<<dim3(24, 8), dim3(32, 8)>>>(Whh1, WT1);
    transpose_k<<<dim3(24, 8), dim3(32, 8)>>>(Whh2, WT2);

    gemm_mma<<<dim3(6, 64), GM_THREADS, GM_SMEM>>>(
        E, NIN, Wih1, NIN, bih1, xg1, G3, tokens, MM, G3, NIN);
    gemm_mma<<<dim3(6, 64), GM_THREADS, GM_SMEM>>>(
        E, NIN, Wih2 + NHID, NHID + NIN, nullptr, xg2, G3, tokens, MM, G3, NIN);

    gru_cluster<<<64, SCAN_THREADS, SC_SMEM>>>(
        xg1, nullptr, WT1, bhh1, h1, nullptr, tail);

    sgemm_nt<<<dim3(6, 1), 256>>>(h1, NHID, Wih2, NHID + NIN, bih2,
                                  hb2, G3, BB, G3, NHID);

    gru_cluster<<<64, SCAN_THREADS, SC_SMEM>>>(
        xg2, hb2, WT2, bhh2, nullptr, preds, nullptr);

    gemm_mma<<<dim3(79, 64), GM_THREADS, GM_SMEM>>>(
        preds, NHID, Wd, NHID, bd, out, NVOC, nullptr, MM, NVOC, NHID);
}

// round 7
// speedup vs baseline: 3.6530x; 1.1192x over previous
#include <cuda_runtime.h>
#include <cuda_bf16.h>
#include <cstdint>

// ---------------------------------------------------------------------------
// Problem constants
// ---------------------------------------------------------------------------
#define NVOC 10000
#define NIN  1024
#define NHID 256
#define G3   768
#define TT   128
#define BB   64
#define MM   (TT*BB)

#define CL 8                  // CTAs per cluster
#define LP 4                  // batch lanes per cluster
#define NCLUST (BB/LP)        // 16 clusters
#define SCAN_THREADS 192

extern __shared__ char dsmem[];

// ---------------------------------------------------------------------------
// Device scratch
// ---------------------------------------------------------------------------
__device__ float g_xg1  [MM * G3];
__device__ float g_xg2  [MM * G3];
__device__ float g_hb2  [BB * G3];
__device__ float g_h1   [BB * NHID];
__device__ float g_preds[MM * NHID];
__device__ float g_WT1  [NHID * G3];
__device__ float g_WT2  [NHID * G3];

// ---------------------------------------------------------------------------
// Helpers
// ---------------------------------------------------------------------------
__device__ __forceinline__ uint32_t smem_u32(const void* p) {
    uint32_t a;
    asm("{ .reg .u64 t; cvta.to.shared.u64 t, %1; cvt.u32.u64 %0, t; }"
        : "=r"(a) : "l"(p));
    return a;
}
__device__ __forceinline__ uint32_t to_tf32_bits(float x) {
    float y;
    asm("cvt.rna.tf32.f32 %0, %1;" : "=f"(y) : "f"(x));
    return __float_as_uint(y);
}
__device__ __forceinline__ unsigned long long f2pack(float lo, float hi) {
    unsigned long long v;
    asm("mov.b64 %0, {%1, %2};" : "=l"(v) : "f"(lo), "f"(hi));
    return v;
}
__device__ __forceinline__ void f2unpack(unsigned long long v, float& lo, float& hi) {
    asm("mov.b64 {%0, %1}, %2;" : "=f"(lo), "=f"(hi) : "l"(v));
}
__device__ __forceinline__ void ffma2(unsigned long long& d, unsigned long long a,
                                      unsigned long long b) {
    asm("fma.rn.f32x2 %0, %1, %2, %3;" : "=l"(d) : "l"(a), "l"(b), "l"(d));
}
__device__ __forceinline__ void mma_tf32(float* d, uint32_t a0, uint32_t a1,
                                         uint32_t a2, uint32_t a3,
                                         uint32_t b0, uint32_t b1) {
    asm volatile(
        "mma.sync.aligned.m16n8k8.row.col.f32.tf32.tf32.f32 "
        "{%0,%1,%2,%3}, {%4,%5,%6,%7}, {%8,%9}, {%0,%1,%2,%3};"
        : "+f"(d[0]), "+f"(d[1]), "+f"(d[2]), "+f"(d[3])
        : "r"(a0), "r"(a1), "r"(a2), "r"(a3), "r"(b0), "r"(b1));
}
__device__ __forceinline__ uint32_t my_ctarank() {
    uint32_t r;
    asm("mov.u32 %0, %%cluster_ctarank;" : "=r"(r));
    return r;
}
__device__ __forceinline__ void dsmem_bcast(uint32_t laddr, float v) {
    uint32_t bits = __float_as_uint(v);
#pragma unroll
    for (int p = 0; p < CL; p++) {
        uint32_t ra;
        asm volatile("mapa.shared::cluster.u32 %0, %1, %2;"
                     : "=r"(ra) : "r"(laddr), "r"(p));
        asm volatile("st.shared::cluster.b32 [%0], %1;"
                     :: "r"(ra), "r"(bits) : "memory");
    }
}

// ---------------------------------------------------------------------------
__global__ void transpose_k(const float* __restrict__ in, float* __restrict__ out) {
    __shared__ float tile[32][33];
    int r0 = blockIdx.x * 32;
    int c0 = blockIdx.y * 32;
    for (int i = threadIdx.y; i < 32; i += 8)
        tile[i][threadIdx.x] = in[(r0 + i) * NHID + (c0 + threadIdx.x)];
    __syncthreads();
    for (int i = threadIdx.y; i < 32; i += 8)
        out[(c0 + i) * G3 + (r0 + threadIdx.x)] = tile[threadIdx.x][i];
}

// ---------------------------------------------------------------------------
// tf32 mma.sync GEMM (trailing mainloop sync removed — double buffering makes
// it redundant: staging of chunk i+2 reuses buffer (i&1) only after the
// post-staging sync of chunk i+1, by which point every warp finished MMA(i)).
// ---------------------------------------------------------------------------
#define GM_THREADS 256
#define GM_SMEM    65536

__global__ void __launch_bounds__(GM_THREADS, 1)
gemm_mma(const float* __restrict__ A, int lda,
         const float* __restrict__ Bw, int ldb,
         const float* __restrict__ bias,
         float* __restrict__ C, int ldc,
         const int* __restrict__ tok,
         int M, int N, int K)
{
    float* smem = (float*)dsmem;
    float* Ab[2] = {smem,         smem + 4096};
    float* Bb[2] = {smem + 8192,  smem + 12288};

    const int tid  = threadIdx.x;
    const int wid  = tid >> 5, lane = tid & 31;
    const int wm   = wid >> 1;
    const int wn   = wid & 1;
    const int gid  = lane >> 2;
    const int tig  = lane & 3;
    const int row0 = blockIdx.y * 128, col0 = blockIdx.x * 128;

    const int sr = tid >> 3;
    const int sc = (tid & 7) * 4;
    const float* Aptr[4];
    const float* Bptr[4];
#pragma unroll
    for (int ps = 0; ps < 4; ps++) {
        int ar = row0 + sr + ps * 32;
        if (ar >= M) ar = M - 1;
        if (tok) ar = tok[ar];
        Aptr[ps] = A + (size_t)ar * lda + sc;
        int br = col0 + sr + ps * 32;
        if (br >= N) br = N - 1;
        Bptr[ps] = Bw + (size_t)br * ldb + sc;
    }
    uint32_t stOff[4];
#pragma unroll
    for (int ps = 0; ps < 4; ps++) {
        int r = sr + ps * 32;
        stOff[ps] = r * 32 + 4 * ((sc >> 2) ^ (r & 7));
    }

    float4 aR[4], bR[4];
#pragma unroll
    for (int ps = 0; ps < 4; ps++) {
        aR[ps] = *(const float4*)(Aptr[ps]);
        bR[ps] = *(const float4*)(Bptr[ps]);
    }

    float acc[2][8][4];
#pragma unroll
    for (int mt = 0; mt < 2; mt++)
#pragma unroll
        for (int nt = 0; nt < 8; nt++)
#pragma unroll
            for (int j = 0; j < 4; j++) acc[mt][nt][j] = 0.f;

    const int NC = K >> 5;
    for (int i = 0; i < NC; i++) {
        float* As = Ab[i & 1];
        float* Bs = Bb[i & 1];
#pragma unroll
        for (int ps = 0; ps < 4; ps++) {
            uint32_t* pa = (uint32_t*)(As + stOff[ps]);
            pa[0] = to_tf32_bits(aR[ps].x);
            pa[1] = to_tf32_bits(aR[ps].y);
            pa[2] = to_tf32_bits(aR[ps].z);
            pa[3] = to_tf32_bits(aR[ps].w);
            uint32_t* pb = (uint32_t*)(Bs + stOff[ps]);
            pb[0] = to_tf32_bits(bR[ps].x);
            pb[1] = to_tf32_bits(bR[ps].y);
            pb[2] = to_tf32_bits(bR[ps].z);
            pb[3] = to_tf32_bits(bR[ps].w);
        }
        __syncthreads();

        if (i + 1 < NC) {
            const int co = (i + 1) * 32;
#pragma unroll
            for (int ps = 0; ps < 4; ps++) {
                aR[ps] = *(const float4*)(Aptr[ps] + co);
                bR[ps] = *(const float4*)(Bptr[ps] + co);
            }
        }

        const uint32_t* Au = (const uint32_t*)As;
        const uint32_t* Bu = (const uint32_t*)Bs;
#pragma unroll
        for (int kk = 0; kk < 4; kk++) {
            const int s0 = 4 * (((kk * 2)    ) ^ gid);
            const int s1 = 4 * (((kk * 2) + 1) ^ gid);
            uint32_t af[2][4];
#pragma unroll
            for (int mt = 0; mt < 2; mt++) {
                int rA = wm * 32 + mt * 16 + gid;
                af[mt][0] = Au[rA * 32 + tig + s0];
                af[mt][1] = Au[(rA + 8) * 32 + tig + s0];
                af[mt][2] = Au[rA * 32 + tig + s1];
                af[mt][3] = Au[(rA + 8) * 32 + tig + s1];
            }
            uint32_t bf[8][2];
#pragma unroll
            for (int nt = 0; nt < 8; nt++) {
                int rB = wn * 64 + nt * 8 + gid;
                bf[nt][0] = Bu[rB * 32 + tig + s0];
                bf[nt][1] = Bu[rB * 32 + tig + s1];
            }
#pragma unroll
            for (int mt = 0; mt < 2; mt++)
#pragma unroll
                for (int nt = 0; nt < 8; nt++)
                    mma_tf32(acc[mt][nt], af[mt][0], af[mt][1], af[mt][2],
                             af[mt][3], bf[nt][0], bf[nt][1]);
        }
        // trailing __syncthreads removed (see header comment)
    }

#pragma unroll
    for (int mt = 0; mt < 2; mt++) {
        int row = row0 + wm * 32 + mt * 16 + gid;
        if (row >= M) continue;
#pragma unroll
        for (int nt = 0; nt < 8; nt++) {
            int col = col0 + wn * 64 + nt * 8 + tig * 2;
            if (col >= N) continue;
            float b0v = bias ? bias[col] : 0.f;
            float* p0 = C + (size_t)row * ldc + col;
            float* p1 = C + (size_t)(row + 8) * ldc + col;
            if (col + 1 < N) {
                float b1v = bias ? bias[col + 1] : 0.f;
                *(float2*)p0 = make_float2(acc[mt][nt][0] + b0v,
                                           acc[mt][nt][1] + b1v);
                if (row + 8 < M)
                    *(float2*)p1 = make_float2(acc[mt][nt][2] + b0v,
                                               acc[mt][nt][3] + b1v);
            } else {
                p0[0] = acc[mt][nt][0] + b0v;
                if (row + 8 < M) p1[0] = acc[mt][nt][2] + b0v;
            }
        }
    }
}

// ---------------------------------------------------------------------------
// fp32 SGEMM (small hb2 GEMM only)
// ---------------------------------------------------------------------------
__global__ void __launch_bounds__(256)
sgemm_nt(const float* __restrict__ A, int lda,
         const float* __restrict__ Bw, int ldb,
         const float* __restrict__ bias,
         float* __restrict__ C, int ldc,
         int M, int N, int K)
{
    __shared__ __align__(16) float As[8][132];
    __shared__ __align__(16) float Bs[8][128];

    const int tid  = threadIdx.x;
    const int row0 = blockIdx.y * 128;
    const int col0 = blockIdx.x * 128;

    const int li = tid >> 1;
    const int lk = (tid & 1) * 4;

    int ar = row0 + li;
    if (ar >= M) ar = M - 1;
    const float* Ap = A + (size_t)ar * lda + lk;

    int brn = col0 + li;
    const bool bval = (brn < N);
    const float* Bp = Bw + (size_t)(bval ? brn : 0) * ldb + lk;

    const int ty = tid >> 4;
    const int tx = tid & 15;

    unsigned long long acc2[8][4];
#pragma unroll
    for (int r = 0; r < 8; r++)
#pragma unroll
        for (int c = 0; c < 4; c++) acc2[r][c] = 0ull;

    for (int k0 = 0; k0 < K; k0 += 8) {
        float4 av = *(const float4*)(Ap + k0);
        float4 bv = bval ? *(const float4*)(Bp + k0) : make_float4(0.f, 0.f, 0.f, 0.f);

        __syncthreads();
        As[lk + 0][li] = av.x; As[lk + 1][li] = av.y;
        As[lk + 2][li] = av.z; As[lk + 3][li] = av.w;
        Bs[lk + 0][li] = bv.x; Bs[lk + 1][li] = bv.y;
        Bs[lk + 2][li] = bv.z; Bs[lk + 3][li] = bv.w;
        __syncthreads();

#pragma unroll
        for (int kk = 0; kk < 8; kk++) {
            float4 a0 = *(const float4*)&As[kk][ty * 8];
            float4 a1 = *(const float4*)&As[kk][ty * 8 + 4];
            const unsigned long long* bp = (const unsigned long long*)&Bs[kk][tx * 8];
            unsigned long long b0 = bp[0], b1 = bp[1], b2 = bp[2], b3 = bp[3];
            float arr[8] = {a0.x, a0.y, a0.z, a0.w, a1.x, a1.y, a1.z, a1.w};
#pragma unroll
            for (int r = 0; r < 8; r++) {
                unsigned long long ad = f2pack(arr[r], arr[r]);
                ffma2(acc2[r][0], ad, b0);
                ffma2(acc2[r][1], ad, b1);
                ffma2(acc2[r][2], ad, b2);
                ffma2(acc2[r][3], ad, b3);
            }
        }
    }

    const bool fullcol = (col0 + 128 <= N);
#pragma unroll
    for (int r = 0; r < 8; r++) {
        int row = row0 + ty * 8 + r;
        if (row >= M) continue;
        float* Cp = C + (size_t)row * ldc + col0 + tx * 8;
        float v[8];
#pragma unroll
        for (int c = 0; c < 4; c++) f2unpack(acc2[r][c], v[2 * c], v[2 * c + 1]);
        if (fullcol) {
            if (bias) {
#pragma unroll
                for (int c = 0; c < 8; c++) v[c] += bias[col0 + tx * 8 + c];
            }
            *(float4*)(Cp)     = make_float4(v[0], v[1], v[2], v[3]);
            *(float4*)(Cp + 4) = make_float4(v[4], v[5], v[6], v[7]);
        } else {
#pragma unroll
            for (int c = 0; c < 8; c++) {
                int col = col0 + tx * 8 + c;
                if (col < N) Cp[c] = v[c] + (bias ? bias[col] : 0.f);
            }
        }
    }
}

// ---------------------------------------------------------------------------
// GRU scan v4: 16 clusters x 8 CTAs (128 SMs). Cluster owns 4 batch lanes;
// CTA rank owns hidden cols [32r,32r+32) with its 96KB W slice in smem.
// GEMV is split-k (two halves per output) + smem partial reduction, keeping
// the FMA pipe the binding resource at ~770 cyc/step/SM.
//
// Smem (bytes):
//   [0,      98304)  w_s [256][3][8] float4
//   [98304, 106624)  h   [2][4][260] float   (double-buffered cluster h)
//   [106624,109696)  sgp [2][3][4][8] float4 (split-k partials)
//   [109696,112768)  xs  [2][4][96] float
//   [112768,114304)  xb  [4][96]    float
// ---------------------------------------------------------------------------
#define SC_W   0
#define SC_H   98304
#define SC_SG  106624
#define SC_XS  109696
#define SC_XB  112768
#define SC_SMEM 114304
#define HB     1040            // 4*260 floats per h buffer

__global__ void __launch_bounds__(SCAN_THREADS) __cluster_dims__(CL, 1, 1)
gru_cluster(const float* __restrict__ xg,
            const float* __restrict__ hb,
            const float* __restrict__ WT,
            const float* __restrict__ bhh,
            float* __restrict__ hfin,
            float* __restrict__ preds,
            float* __restrict__ tail)
{
    float4* w_s  = (float4*)(dsmem + SC_W);
    float*  hbuf = (float*) (dsmem + SC_H);
    float4* sgp4 = (float4*)(dsmem + SC_SG);
    float*  sgf  = (float*) (dsmem + SC_SG);
    float*  xs   = (float*) (dsmem + SC_XS);
    float*  xb   = (float*) (dsmem + SC_XB);

    const int tid  = threadIdx.x;
    const int rank = (int)my_ctarank();
    const int cid  = blockIdx.x / CL;
    const int b0   = cid * LP;
    const int colbase = rank * 32;

    for (int i = tid; i < 256 * 24; i += SCAN_THREADS) {
        int k = i / 24, j = i - 24 * k;
        int g = j >> 3, quad = j & 7;
        w_s[i] = *(const float4*)(WT + (size_t)k * G3 + g * NHID + colbase + quad * 4);
    }
    for (int i = tid; i < 2 * HB; i += SCAN_THREADS) hbuf[i] = 0.f;
    for (int i = tid; i < LP * 96; i += SCAN_THREADS) {
        int b = i / 96, j = i - 96 * b;
        int g = j >> 5, c = j & 31;
        xb[i] = hb ? hb[(size_t)(b0 + b) * G3 + g * NHID + colbase + c] : 0.f;
    }

    // GEMV mapping: q (gate) 0..2, within 64: kh = bit5, quad = bits2..4, gb = bits0..1
    const int q    = tid / 64;
    const int r64  = tid - q * 64;
    const int kh   = r64 >> 5;
    const int quad = (r64 >> 2) & 7;
    const int gb   = r64 & 3;
    const int k0   = kh * 128;

    unsigned long long bhA = 0ull, bhB = 0ull;
    if (kh == 0) {
        const float4 bh4 = *(const float4*)(bhh + q * NHID + colbase + quad * 4);
        bhA = f2pack(bh4.x, bh4.y);
        bhB = f2pack(bh4.z, bh4.w);
    }

    // xg prefetch mapping (threads 0..95)
    const int pb = tid / 24;
    const int pj = tid - 24 * pb;
    const int pg = pj >> 3, pf = pj & 7;
    const bool pfv = (tid < 96);
    const float* xgp = pfv
        ? xg + (size_t)(b0 + pb) * G3 + pg * NHID + colbase + pf * 4 : xg;
    float* xss = xs + (pfv ? pb * 96 + pg * 32 + pf * 4 : 0);

    __syncthreads();
    asm volatile("barrier.cluster.arrive.aligned;" ::: "memory");
    asm volatile("barrier.cluster.wait.aligned;"   ::: "memory");

    float4 v = pfv ? *(const float4*)(xgp) : make_float4(0.f, 0.f, 0.f, 0.f);

    for (int t = 0; t < TT; t++) {
        const int cur = t & 1;

        if (pfv) {
            *(float4*)(xss + cur * 384) = v;
            if (t + 1 < TT) v = *(const float4*)(xgp + (size_t)(t + 1) * BB * G3);
        }

        // ---- split-k GEMV over k in [k0, k0+128) ----
        const float* hc = hbuf + cur * HB;
        unsigned long long accA = bhA, accB = bhB;
        const float4* wp = w_s + q * 8 + quad;
        const float*  hp = hc + gb * 260 + k0;
#pragma unroll 16
        for (int kk = 0; kk < 64; kk++) {
            ulonglong2 w0 = *(const ulonglong2*)(wp + (k0 + 2 * kk)     * 24);
            ulonglong2 w1 = *(const ulonglong2*)(wp + (k0 + 2 * kk + 1) * 24);
            float2 h2 = *(const float2*)(hp + 2 * kk);
            unsigned long long h0 = f2pack(h2.x, h2.x);
            unsigned long long h1 = f2pack(h2.y, h2.y);
            ffma2(accA, w0.x, h0);
            ffma2(accB, w0.y, h0);
            ffma2(accA, w1.x, h1);
            ffma2(accB, w1.y, h1);
        }
        float4 accv;
        f2unpack(accA, accv.x, accv.y);
        f2unpack(accB, accv.z, accv.w);
        sgp4[kh * 96 + q * 32 + gb * 8 + quad] = accv;
        __syncthreads();

        // ---- phase 2: reduce split-k, gates, update, DSMEM broadcast ----
        if (tid < LP * 32) {
            int tb = tid >> 5;
            int c  = tid & 31;
            const float* xr  = xs + cur * 384 + tb * 96;
            const float* xbr = xb + tb * 96;
            int base = (tb * 8 + (c >> 2)) * 4 + (c & 3);
            float hgr = sgf[base]             + sgf[384 + base];
            float hgz = sgf[128 + base]       + sgf[384 + 128 + base];
            float hgn = sgf[256 + base]       + sgf[384 + 256 + base];
            float gr = xr[c]      + xbr[c];
            float gz = xr[32 + c] + xbr[32 + c];
            float gn = xr[64 + c] + xbr[64 + c];
            float ho = hc[tb * 260 + colbase + c];
            float rr = 1.f / (1.f + __expf(-(gr + hgr)));
            float zz = 1.f / (1.f + __expf(-(gz + hgz)));
            float nn = tanhf(gn + rr * hgn);
            float hn = (1.f - zz) * nn + zz * ho;
            if (preds)
                preds[(size_t)(t * BB + b0 + tb) * NHID + colbase + c] = hn;
            if (t == TT - 1) {
                if (hfin) hfin[(size_t)(b0 + tb) * NHID + colbase + c] = hn;
                if (tail) tail[(size_t)(b0 + tb) * NHID + colbase + c] = hn;
            } else {
                uint32_t laddr = smem_u32(
                    hbuf + (1 - cur) * HB + tb * 260 + colbase + c);
                dsmem_bcast(laddr, hn);
            }
        }

        if (t == TT - 1) break;
        asm volatile("barrier.cluster.arrive.aligned;" ::: "memory");
        asm volatile("barrier.cluster.wait.aligned;"   ::: "memory");
    }
}

// ---------------------------------------------------------------------------
// Launcher
// ---------------------------------------------------------------------------
extern "C" void kernel_launch(void* const* d_in, const int* in_sizes, int n_in,
                              void* d_out, int out_size)
{
    const int*   tokens = (const int*)  d_in[0];
    const float* E      = (const float*)d_in[1];
    const float* Wih1   = (const float*)d_in[2];
    const float* Whh1   = (const float*)d_in[3];
    const float* bih1   = (const float*)d_in[4];
    const float* bhh1   = (const float*)d_in[5];
    const float* Wih2   = (const float*)d_in[6];
    const float* Whh2   = (const float*)d_in[7];
    const float* bih2   = (const float*)d_in[8];
    const float* bhh2   = (const float*)d_in[9];
    // d_in[10..14] dead (attention context == h1 exactly)
    const float* Wd     = (const float*)d_in[15];
    const float* bd     = (const float*)d_in[16];
    float* out = (float*)d_out;

    float *xg1, *xg2, *hb2, *h1, *preds, *WT1, *WT2;
    cudaGetSymbolAddress((void**)&xg1,   g_xg1);
    cudaGetSymbolAddress((void**)&xg2,   g_xg2);
    cudaGetSymbolAddress((void**)&hb2,   g_hb2);
    cudaGetSymbolAddress((void**)&h1,    g_h1);
    cudaGetSymbolAddress((void**)&preds, g_preds);
    cudaGetSymbolAddress((void**)&WT1,   g_WT1);
    cudaGetSymbolAddress((void**)&WT2,   g_WT2);

    cudaFuncSetAttribute(gru_cluster, cudaFuncAttributeMaxDynamicSharedMemorySize,
                         SC_SMEM);
    cudaFuncSetAttribute(gemm_mma, cudaFuncAttributeMaxDynamicSharedMemorySize,
                         GM_SMEM);

    float* tail = nullptr;
    if (out_size >= MM * NVOC + BB * NHID) tail = out + (size_t)MM * NVOC;

    transpose_k<<<dim3(24, 8), dim3(32, 8)>>>(Whh1, WT1);
    transpose_k<<<dim3(24, 8), dim3(32, 8)>>>(Whh2, WT2);

    gemm_mma<<<dim3(6, 64), GM_THREADS, GM_SMEM>>>(
        E, NIN, Wih1, NIN, bih1, xg1, G3, tokens, MM, G3, NIN);
    gemm_mma<<<dim3(6, 64), GM_THREADS, GM_SMEM>>>(
        E, NIN, Wih2 + NHID, NHID + NIN, nullptr, xg2, G3, tokens, MM, G3, NIN);

    gru_cluster<<<NCLUST * CL, SCAN_THREADS, SC_SMEM>>>(
        xg1, nullptr, WT1, bhh1, h1, nullptr, tail);

    sgemm_nt<<<dim3(6, 1), 256>>>(h1, NHID, Wih2, NHID + NIN, bih2,
                                  hb2, G3, BB, G3, NHID);

    gru_cluster<<<NCLUST * CL, SCAN_THREADS, SC_SMEM>>>(
        xg2, hb2, WT2, bhh2, nullptr, preds, nullptr);

    gemm_mma<<<dim3(79, 64), GM_THREADS, GM_SMEM>>>(
        preds, NHID, Wd, NHID, bd, out, NVOC, nullptr, MM, NVOC, NHID);
}

// round 8
// speedup vs baseline: 3.9995x; 1.0948x over previous
#include <cuda_runtime.h>
#include <cuda_bf16.h>
#include <cstdint>

// ---------------------------------------------------------------------------
// Problem constants
// ---------------------------------------------------------------------------
#define NVOC 10000
#define NIN  1024
#define NHID 256
#define G3   768
#define TT   128
#define BB   64
#define MM   (TT*BB)

#define CL 8                  // CTAs per cluster
#define LP 4                  // batch lanes per cluster
#define NCLUST (BB/LP)        // 16 clusters
#define SCAN_THREADS 384

extern __shared__ char dsmem[];

// ---------------------------------------------------------------------------
// Device scratch
// ---------------------------------------------------------------------------
__device__ float g_xg1  [MM * G3];
__device__ float g_xg2  [MM * G3];
__device__ float g_hb2  [BB * G3];
__device__ float g_h1   [BB * NHID];
__device__ float g_preds[MM * NHID];
__device__ float g_WT1  [NHID * G3];
__device__ float g_WT2  [NHID * G3];

// ---------------------------------------------------------------------------
// Helpers
// ---------------------------------------------------------------------------
__device__ __forceinline__ uint32_t smem_u32(const void* p) {
    uint32_t a;
    asm("{ .reg .u64 t; cvta.to.shared.u64 t, %1; cvt.u32.u64 %0, t; }"
        : "=r"(a) : "l"(p));
    return a;
}
__device__ __forceinline__ uint32_t to_tf32_bits(float x) {
    float y;
    asm("cvt.rna.tf32.f32 %0, %1;" : "=f"(y) : "f"(x));
    return __float_as_uint(y);
}
__device__ __forceinline__ unsigned long long f2pack(float lo, float hi) {
    unsigned long long v;
    asm("mov.b64 %0, {%1, %2};" : "=l"(v) : "f"(lo), "f"(hi));
    return v;
}
__device__ __forceinline__ void f2unpack(unsigned long long v, float& lo, float& hi) {
    asm("mov.b64 {%0, %1}, %2;" : "=f"(lo), "=f"(hi) : "l"(v));
}
__device__ __forceinline__ void ffma2(unsigned long long& d, unsigned long long a,
                                      unsigned long long b) {
    asm("fma.rn.f32x2 %0, %1, %2, %3;" : "=l"(d) : "l"(a), "l"(b), "l"(d));
}
__device__ __forceinline__ void mma_tf32(float* d, uint32_t a0, uint32_t a1,
                                         uint32_t a2, uint32_t a3,
                                         uint32_t b0, uint32_t b1) {
    asm volatile(
        "mma.sync.aligned.m16n8k8.row.col.f32.tf32.tf32.f32 "
        "{%0,%1,%2,%3}, {%4,%5,%6,%7}, {%8,%9}, {%0,%1,%2,%3};"
        : "+f"(d[0]), "+f"(d[1]), "+f"(d[2]), "+f"(d[3])
        : "r"(a0), "r"(a1), "r"(a2), "r"(a3), "r"(b0), "r"(b1));
}
__device__ __forceinline__ uint32_t my_ctarank() {
    uint32_t r;
    asm("mov.u32 %0, %%cluster_ctarank;" : "=r"(r));
    return r;
}
__device__ __forceinline__ void dsmem_bcast(uint32_t laddr, float v) {
    uint32_t bits = __float_as_uint(v);
#pragma unroll
    for (int p = 0; p < CL; p++) {
        uint32_t ra;
        asm volatile("mapa.shared::cluster.u32 %0, %1, %2;"
                     : "=r"(ra) : "r"(laddr), "r"(p));
        asm volatile("st.shared::cluster.b32 [%0], %1;"
                     :: "r"(ra), "r"(bits) : "memory");
    }
}
__device__ __forceinline__ void cp_async16(uint32_t dst, const void* src) {
    asm volatile("cp.async.cg.shared.global [%0], [%1], 16;"
                 :: "r"(dst), "l"(src) : "memory");
}
#define CP_COMMIT() asm volatile("cp.async.commit_group;" ::: "memory")
#define CP_WAIT2()  asm volatile("cp.async.wait_group 2;" ::: "memory")

// ---------------------------------------------------------------------------
__global__ void transpose_k(const float* __restrict__ in, float* __restrict__ out) {
    __shared__ float tile[32][33];
    int r0 = blockIdx.x * 32;
    int c0 = blockIdx.y * 32;
    for (int i = threadIdx.y; i < 32; i += 8)
        tile[i][threadIdx.x] = in[(r0 + i) * NHID + (c0 + threadIdx.x)];
    __syncthreads();
    for (int i = threadIdx.y; i < 32; i += 8)
        out[(c0 + i) * G3 + (r0 + threadIdx.x)] = tile[threadIdx.x][i];
}

// ---------------------------------------------------------------------------
// tf32 mma.sync GEMM with 4-stage cp.async pipeline.
// Smem holds raw fp32 (cp.async 16B); tf32 cvt happens at fragment load, so
// numerics are identical to the register-staged version.
// Group accounting: prologue commits 3 groups; every loop iter commits exactly
// one (possibly empty) group, so wait_group 2 at iter i retires chunk i.
// ---------------------------------------------------------------------------
#define GM_THREADS 256
#define NST 4
#define GM_SMEM (NST * 32768)

__global__ void __launch_bounds__(GM_THREADS, 1)
gemm_mma(const float* __restrict__ A, int lda,
         const float* __restrict__ Bw, int ldb,
         const float* __restrict__ bias,
         float* __restrict__ C, int ldc,
         const int* __restrict__ tok,
         int M, int N, int K)
{
    float* smem = (float*)dsmem;
    const uint32_t sbase = smem_u32(dsmem);

    const int tid  = threadIdx.x;
    const int wid  = tid >> 5, lane = tid & 31;
    const int wm   = wid >> 1;
    const int wn   = wid & 1;
    const int gid  = lane >> 2;
    const int tig  = lane & 3;
    const int row0 = blockIdx.y * 128, col0 = blockIdx.x * 128;

    const int sr = tid >> 3;
    const int sc = (tid & 7) * 4;
    const float* Aptr[4];
    const float* Bptr[4];
#pragma unroll
    for (int ps = 0; ps < 4; ps++) {
        int ar = row0 + sr + ps * 32;
        if (ar >= M) ar = M - 1;
        if (tok) ar = tok[ar];
        Aptr[ps] = A + (size_t)ar * lda + sc;
        int br = col0 + sr + ps * 32;
        if (br >= N) br = N - 1;
        Bptr[ps] = Bw + (size_t)br * ldb + sc;
    }
    uint32_t stOff[4];
#pragma unroll
    for (int ps = 0; ps < 4; ps++) {
        int r = sr + ps * 32;
        stOff[ps] = (r * 32 + 4 * ((sc >> 2) ^ (r & 7))) * 4;  // bytes
    }

    const int NC = K >> 5;

    auto issue = [&](int idx) {
        uint32_t ab = sbase + (uint32_t)(idx & (NST - 1)) * 32768u;
        const int co = idx * 32;
#pragma unroll
        for (int ps = 0; ps < 4; ps++) {
            cp_async16(ab + stOff[ps], Aptr[ps] + co);
            cp_async16(ab + 16384u + stOff[ps], Bptr[ps] + co);
        }
        CP_COMMIT();
    };

    // prologue: 3 stages in flight
    issue(0); issue(1); issue(2);

    float acc[2][8][4];
#pragma unroll
    for (int mt = 0; mt < 2; mt++)
#pragma unroll
        for (int nt = 0; nt < 8; nt++)
#pragma unroll
            for (int j = 0; j < 4; j++) acc[mt][nt][j] = 0.f;

    for (int i = 0; i < NC; i++) {
        CP_WAIT2();
        __syncthreads();

        const float* As = smem + (size_t)(i & (NST - 1)) * 8192;
        const float* Bs = As + 4096;

#pragma unroll
        for (int kk = 0; kk < 4; kk++) {
            const int s0 = 4 * (((kk * 2)    ) ^ gid);
            const int s1 = 4 * (((kk * 2) + 1) ^ gid);
            uint32_t af[2][4];
#pragma unroll
            for (int mt = 0; mt < 2; mt++) {
                int rA = wm * 32 + mt * 16 + gid;
                af[mt][0] = to_tf32_bits(As[rA * 32 + tig + s0]);
                af[mt][1] = to_tf32_bits(As[(rA + 8) * 32 + tig + s0]);
                af[mt][2] = to_tf32_bits(As[rA * 32 + tig + s1]);
                af[mt][3] = to_tf32_bits(As[(rA + 8) * 32 + tig + s1]);
            }
            uint32_t bf[8][2];
#pragma unroll
            for (int nt = 0; nt < 8; nt++) {
                int rB = wn * 64 + nt * 8 + gid;
                bf[nt][0] = to_tf32_bits(Bs[rB * 32 + tig + s0]);
                bf[nt][1] = to_tf32_bits(Bs[rB * 32 + tig + s1]);
            }
#pragma unroll
            for (int mt = 0; mt < 2; mt++)
#pragma unroll
                for (int nt = 0; nt < 8; nt++)
                    mma_tf32(acc[mt][nt], af[mt][0], af[mt][1], af[mt][2],
                             af[mt][3], bf[nt][0], bf[nt][1]);
        }

        if (i + 3 < NC) issue(i + 3);
        else            CP_COMMIT();   // empty group keeps accounting uniform
    }

    // epilogue
#pragma unroll
    for (int mt = 0; mt < 2; mt++) {
        int row = row0 + wm * 32 + mt * 16 + gid;
        if (row >= M) continue;
#pragma unroll
        for (int nt = 0; nt < 8; nt++) {
            int col = col0 + wn * 64 + nt * 8 + tig * 2;
            if (col >= N) continue;
            float b0v = bias ? bias[col] : 0.f;
            float* p0 = C + (size_t)row * ldc + col;
            float* p1 = C + (size_t)(row + 8) * ldc + col;
            if (col + 1 < N) {
                float b1v = bias ? bias[col + 1] : 0.f;
                *(float2*)p0 = make_float2(acc[mt][nt][0] + b0v,
                                           acc[mt][nt][1] + b1v);
                if (row + 8 < M)
                    *(float2*)p1 = make_float2(acc[mt][nt][2] + b0v,
                                               acc[mt][nt][3] + b1v);
            } else {
                p0[0] = acc[mt][nt][0] + b0v;
                if (row + 8 < M) p1[0] = acc[mt][nt][2] + b0v;
            }
        }
    }
}

// ---------------------------------------------------------------------------
// fp32 SGEMM (small hb2 GEMM only)
// ---------------------------------------------------------------------------
__global__ void __launch_bounds__(256)
sgemm_nt(const float* __restrict__ A, int lda,
         const float* __restrict__ Bw, int ldb,
         const float* __restrict__ bias,
         float* __restrict__ C, int ldc,
         int M, int N, int K)
{
    __shared__ __align__(16) float As[8][132];
    __shared__ __align__(16) float Bs[8][128];

    const int tid  = threadIdx.x;
    const int row0 = blockIdx.y * 128;
    const int col0 = blockIdx.x * 128;

    const int li = tid >> 1;
    const int lk = (tid & 1) * 4;

    int ar = row0 + li;
    if (ar >= M) ar = M - 1;
    const float* Ap = A + (size_t)ar * lda + lk;

    int brn = col0 + li;
    const bool bval = (brn < N);
    const float* Bp = Bw + (size_t)(bval ? brn : 0) * ldb + lk;

    const int ty = tid >> 4;
    const int tx = tid & 15;

    unsigned long long acc2[8][4];
#pragma unroll
    for (int r = 0; r < 8; r++)
#pragma unroll
        for (int c = 0; c < 4; c++) acc2[r][c] = 0ull;

    for (int k0 = 0; k0 < K; k0 += 8) {
        float4 av = *(const float4*)(Ap + k0);
        float4 bv = bval ? *(const float4*)(Bp + k0) : make_float4(0.f, 0.f, 0.f, 0.f);

        __syncthreads();
        As[lk + 0][li] = av.x; As[lk + 1][li] = av.y;
        As[lk + 2][li] = av.z; As[lk + 3][li] = av.w;
        Bs[lk + 0][li] = bv.x; Bs[lk + 1][li] = bv.y;
        Bs[lk + 2][li] = bv.z; Bs[lk + 3][li] = bv.w;
        __syncthreads();

#pragma unroll
        for (int kk = 0; kk < 8; kk++) {
            float4 a0 = *(const float4*)&As[kk][ty * 8];
            float4 a1 = *(const float4*)&As[kk][ty * 8 + 4];
            const unsigned long long* bp = (const unsigned long long*)&Bs[kk][tx * 8];
            unsigned long long b0 = bp[0], b1 = bp[1], b2 = bp[2], b3 = bp[3];
            float arr[8] = {a0.x, a0.y, a0.z, a0.w, a1.x, a1.y, a1.z, a1.w};
#pragma unroll
            for (int r = 0; r < 8; r++) {
                unsigned long long ad = f2pack(arr[r], arr[r]);
                ffma2(acc2[r][0], ad, b0);
                ffma2(acc2[r][1], ad, b1);
                ffma2(acc2[r][2], ad, b2);
                ffma2(acc2[r][3], ad, b3);
            }
        }
    }

    const bool fullcol = (col0 + 128 <= N);
#pragma unroll
    for (int r = 0; r < 8; r++) {
        int row = row0 + ty * 8 + r;
        if (row >= M) continue;
        float* Cp = C + (size_t)row * ldc + col0 + tx * 8;
        float v[8];
#pragma unroll
        for (int c = 0; c < 4; c++) f2unpack(acc2[r][c], v[2 * c], v[2 * c + 1]);
        if (fullcol) {
            if (bias) {
#pragma unroll
                for (int c = 0; c < 8; c++) v[c] += bias[col0 + tx * 8 + c];
            }
            *(float4*)(Cp)     = make_float4(v[0], v[1], v[2], v[3]);
            *(float4*)(Cp + 4) = make_float4(v[4], v[5], v[6], v[7]);
        } else {
#pragma unroll
            for (int c = 0; c < 8; c++) {
                int col = col0 + tx * 8 + c;
                if (col < N) Cp[c] = v[c] + (bias ? bias[col] : 0.f);
            }
        }
    }
}

// ---------------------------------------------------------------------------
// GRU scan v5: 16 clusters x 8 CTAs, 384 threads (12 warps = 3/SMSP balanced).
// 4-way split-k GEMV; xs staging + xg prefetch hidden between cluster arrive
// and wait. CTA owns 32 hidden cols; full W slice + cluster h in smem.
//
// Smem (bytes):
//   [0,      98304)  w_s [256][3][8] float4
//   [98304, 106624)  h   [2][4][260] float
//   [106624,112768)  sgp [4kh][3q][4gb][8quad] float4
//   [112768,115840)  xs  [2][4][96] float
//   [115840,117376)  xb  [4][96]    float
// ---------------------------------------------------------------------------
#define SC_W   0
#define SC_H   98304
#define SC_SG  106624
#define SC_XS  112768
#define SC_XB  115840
#define SC_SMEM 117376
#define HB     1040

__global__ void __launch_bounds__(SCAN_THREADS) __cluster_dims__(CL, 1, 1)
gru_cluster(const float* __restrict__ xg,
            const float* __restrict__ hb,
            const float* __restrict__ WT,
            const float* __restrict__ bhh,
            float* __restrict__ hfin,
            float* __restrict__ preds,
            float* __restrict__ tail)
{
    float4* w_s  = (float4*)(dsmem + SC_W);
    float*  hbuf = (float*) (dsmem + SC_H);
    float4* sgp4 = (float4*)(dsmem + SC_SG);
    float*  sgf  = (float*) (dsmem + SC_SG);
    float*  xs   = (float*) (dsmem + SC_XS);
    float*  xb   = (float*) (dsmem + SC_XB);

    const int tid  = threadIdx.x;
    const int rank = (int)my_ctarank();
    const int cid  = blockIdx.x / CL;
    const int b0   = cid * LP;
    const int colbase = rank * 32;

    for (int i = tid; i < 256 * 24; i += SCAN_THREADS) {
        int k = i / 24, j = i - 24 * k;
        int g = j >> 3, quad = j & 7;
        w_s[i] = *(const float4*)(WT + (size_t)k * G3 + g * NHID + colbase + quad * 4);
    }
    for (int i = tid; i < (2 * HB) / 4; i += SCAN_THREADS)
        ((float4*)hbuf)[i] = make_float4(0.f, 0.f, 0.f, 0.f);
    for (int i = tid; i < LP * 96; i += SCAN_THREADS) {
        int b = i / 96, j = i - 96 * b;
        int g = j >> 5, c = j & 31;
        xb[i] = hb ? hb[(size_t)(b0 + b) * G3 + g * NHID + colbase + c] : 0.f;
    }

    // GEMV mapping: tid = q*128 + kh*32 + quad*4 + gb
    const int q    = tid >> 7;          // 0..2
    const int r128 = tid & 127;
    const int kh   = r128 >> 5;         // 0..3 (k quarter)
    const int quad = (r128 >> 2) & 7;   // 0..7
    const int gb   = r128 & 3;          // 0..3 (batch lane)
    const int k0   = kh * 64;

    unsigned long long bhA = 0ull, bhB = 0ull;
    if (kh == 0) {
        const float4 bh4 = *(const float4*)(bhh + q * NHID + colbase + quad * 4);
        bhA = f2pack(bh4.x, bh4.y);
        bhB = f2pack(bh4.z, bh4.w);
    }

    // xg prefetch mapping (threads 0..95)
    const int pb = tid / 24;
    const int pj = tid - 24 * pb;
    const int pg = pj >> 3, pf = pj & 7;
    const bool pfv = (tid < 96);
    const float* xgp = pfv
        ? xg + (size_t)(b0 + pb) * G3 + pg * NHID + colbase + pf * 4 : xg;
    float* xss = xs + (pfv ? pb * 96 + pg * 32 + pf * 4 : 0);

    float4 v = pfv ? *(const float4*)(xgp) : make_float4(0.f, 0.f, 0.f, 0.f);
    if (pfv) {
        *(float4*)(xss) = v;                         // xs slot 0 (t=0)
        v = *(const float4*)(xgp + (size_t)BB * G3); // t=1
    }

    __syncthreads();
    asm volatile("barrier.cluster.arrive.aligned;" ::: "memory");
    asm volatile("barrier.cluster.wait.aligned;"   ::: "memory");

    for (int t = 0; t < TT; t++) {
        const int cur = t & 1;
        const int nxt = cur ^ 1;

        // ---- 4-way split-k GEMV over k in [k0, k0+64) ----
        const float* hc = hbuf + cur * HB;
        unsigned long long accA = bhA, accB = bhB;
        const float4* wp = w_s + (q * 8 + quad) + k0 * 24;
        const float*  hp = hc + gb * 260 + k0;
#pragma unroll
        for (int kk = 0; kk < 16; kk++) {
            const float4* wb = wp + (4 * kk) * 24;
            ulonglong2 w0 = *(const ulonglong2*)(wb);
            ulonglong2 w1 = *(const ulonglong2*)(wb + 24);
            ulonglong2 w2 = *(const ulonglong2*)(wb + 48);
            ulonglong2 w3 = *(const ulonglong2*)(wb + 72);
            float4 h4 = *(const float4*)(hp + 4 * kk);
            unsigned long long h0 = f2pack(h4.x, h4.x);
            unsigned long long h1 = f2pack(h4.y, h4.y);
            unsigned long long h2 = f2pack(h4.z, h4.z);
            unsigned long long h3 = f2pack(h4.w, h4.w);
            ffma2(accA, w0.x, h0); ffma2(accB, w0.y, h0);
            ffma2(accA, w1.x, h1); ffma2(accB, w1.y, h1);
            ffma2(accA, w2.x, h2); ffma2(accB, w2.y, h2);
            ffma2(accA, w3.x, h3); ffma2(accB, w3.y, h3);
        }
        float4 accv;
        f2unpack(accA, accv.x, accv.y);
        f2unpack(accB, accv.z, accv.w);
        sgp4[kh * 96 + q * 32 + gb * 8 + quad] = accv;
        __syncthreads();

        // ---- phase 2: reduce split-k, gates, update, DSMEM broadcast ----
        if (tid < LP * 32) {
            int tb = tid >> 5;
            int c  = tid & 31;
            const float* xr  = xs + cur * 384 + tb * 96;
            const float* xbr = xb + tb * 96;
            int base = tb * 32 + c;
            float hgr = sgf[base]       + sgf[384 + base]
                      + sgf[768 + base] + sgf[1152 + base];
            float hgz = sgf[128 + base]       + sgf[384 + 128 + base]
                      + sgf[768 + 128 + base] + sgf[1152 + 128 + base];
            float hgn = sgf[256 + base]       + sgf[384 + 256 + base]
                      + sgf[768 + 256 + base] + sgf[1152 + 256 + base];
            float gr = xr[c]      + xbr[c];
            float gz = xr[32 + c] + xbr[32 + c];
            float gn = xr[64 + c] + xbr[64 + c];
            float ho = hc[tb * 260 + colbase + c];
            float rr = 1.f / (1.f + __expf(-(gr + hgr)));
            float zz = 1.f / (1.f + __expf(-(gz + hgz)));
            float nn = tanhf(gn + rr * hgn);
            float hn = (1.f - zz) * nn + zz * ho;
            if (preds)
                preds[(size_t)(t * BB + b0 + tb) * NHID + colbase + c] = hn;
            if (t == TT - 1) {
                if (hfin) hfin[(size_t)(b0 + tb) * NHID + colbase + c] = hn;
                if (tail) tail[(size_t)(b0 + tb) * NHID + colbase + c] = hn;
            } else {
                uint32_t laddr = smem_u32(
                    hbuf + nxt * HB + tb * 260 + colbase + c);
                dsmem_bcast(laddr, hn);
            }
        }

        if (t == TT - 1) break;
        asm volatile("barrier.cluster.arrive.aligned;" ::: "memory");
        // hide barrier latency: stage next step's input gates, prefetch t+2
        if (pfv) {
            *(float4*)(xss + nxt * 384) = v;
            if (t + 2 < TT)
                v = *(const float4*)(xgp + (size_t)(t + 2) * BB * G3);
        }
        asm volatile("barrier.cluster.wait.aligned;"   ::: "memory");
    }
}

// ---------------------------------------------------------------------------
// Launcher
// ---------------------------------------------------------------------------
extern "C" void kernel_launch(void* const* d_in, const int* in_sizes, int n_in,
                              void* d_out, int out_size)
{
    const int*   tokens = (const int*)  d_in[0];
    const float* E      = (const float*)d_in[1];
    const float* Wih1   = (const float*)d_in[2];
    const float* Whh1   = (const float*)d_in[3];
    const float* bih1   = (const float*)d_in[4];
    const float* bhh1   = (const float*)d_in[5];
    const float* Wih2   = (const float*)d_in[6];
    const float* Whh2   = (const float*)d_in[7];
    const float* bih2   = (const float*)d_in[8];
    const float* bhh2   = (const float*)d_in[9];
    // d_in[10..14] dead (attention context == h1 exactly)
    const float* Wd     = (const float*)d_in[15];
    const float* bd     = (const float*)d_in[16];
    float* out = (float*)d_out;

    float *xg1, *xg2, *hb2, *h1, *preds, *WT1, *WT2;
    cudaGetSymbolAddress((void**)&xg1,   g_xg1);
    cudaGetSymbolAddress((void**)&xg2,   g_xg2);
    cudaGetSymbolAddress((void**)&hb2,   g_hb2);
    cudaGetSymbolAddress((void**)&h1,    g_h1);
    cudaGetSymbolAddress((void**)&preds, g_preds);
    cudaGetSymbolAddress((void**)&WT1,   g_WT1);
    cudaGetSymbolAddress((void**)&WT2,   g_WT2);

    cudaFuncSetAttribute(gru_cluster, cudaFuncAttributeMaxDynamicSharedMemorySize,
                         SC_SMEM);
    cudaFuncSetAttribute(gemm_mma, cudaFuncAttributeMaxDynamicSharedMemorySize,
                         GM_SMEM);

    float* tail = nullptr;
    if (out_size >= MM * NVOC + BB * NHID) tail = out + (size_t)MM * NVOC;

    transpose_k<<<dim3(24, 8), dim3(32, 8)>>>(Whh1, WT1);
    transpose_k<<<dim3(24, 8), dim3(32, 8)>>>(Whh2, WT2);

    gemm_mma<<<dim3(6, 64), GM_THREADS, GM_SMEM>>>(
        E, NIN, Wih1, NIN, bih1, xg1, G3, tokens, MM, G3, NIN);
    gemm_mma<<<dim3(6, 64), GM_THREADS, GM_SMEM>>>(
        E, NIN, Wih2 + NHID, NHID + NIN, nullptr, xg2, G3, tokens, MM, G3, NIN);

    gru_cluster<<<NCLUST * CL, SCAN_THREADS, SC_SMEM>>>(
        xg1, nullptr, WT1, bhh1, h1, nullptr, tail);

    sgemm_nt<<<dim3(6, 1), 256>>>(h1, NHID, Wih2, NHID + NIN, bih2,
                                  hb2, G3, BB, G3, NHID);

    gru_cluster<<<NCLUST * CL, SCAN_THREADS, SC_SMEM>>>(
        xg2, hb2, WT2, bhh2, nullptr, preds, nullptr);

    gemm_mma<<<dim3(79, 64), GM_THREADS, GM_SMEM>>>(
        preds, NHID, Wd, NHID, bd, out, NVOC, nullptr, MM, NVOC, NHID);
}

// round 9
// speedup vs baseline: 4.5704x; 1.1428x over previous
#include <cuda_runtime.h>
#include <cuda_bf16.h>
#include <cstdint>

// ---------------------------------------------------------------------------
// Problem constants
// ---------------------------------------------------------------------------
#define NVOC 10000
#define NIN  1024
#define NHID 256
#define G3   768
#define TT   128
#define BB   64
#define MM   (TT*BB)

#define CL 8                  // CTAs per cluster
#define LP 4                  // batch lanes per cluster
#define NCLUST (BB/LP)        // 16 clusters
#define SCAN_THREADS 384

extern __shared__ char dsmem[];

// ---------------------------------------------------------------------------
// Device scratch
// ---------------------------------------------------------------------------
__device__ float g_xg1  [MM * G3];
__device__ float g_xg2  [MM * G3];
__device__ float g_hb2  [BB * G3];
__device__ float g_h1   [BB * NHID];
__device__ float g_preds[MM * NHID];
__device__ float g_WT1  [NHID * G3];
__device__ float g_WT2  [NHID * G3];

// ---------------------------------------------------------------------------
// Helpers
// ---------------------------------------------------------------------------
__device__ __forceinline__ uint32_t smem_u32(const void* p) {
    uint32_t a;
    asm("{ .reg .u64 t; cvta.to.shared.u64 t, %1; cvt.u32.u64 %0, t; }"
        : "=r"(a) : "l"(p));
    return a;
}
__device__ __forceinline__ uint32_t to_tf32_bits(float x) {
    float y;
    asm("cvt.rna.tf32.f32 %0, %1;" : "=f"(y) : "f"(x));
    return __float_as_uint(y);
}
__device__ __forceinline__ unsigned long long f2pack(float lo, float hi) {
    unsigned long long v;
    asm("mov.b64 %0, {%1, %2};" : "=l"(v) : "f"(lo), "f"(hi));
    return v;
}
__device__ __forceinline__ void f2unpack(unsigned long long v, float& lo, float& hi) {
    asm("mov.b64 {%0, %1}, %2;" : "=f"(lo), "=f"(hi) : "l"(v));
}
__device__ __forceinline__ void ffma2(unsigned long long& d, unsigned long long a,
                                      unsigned long long b) {
    asm("fma.rn.f32x2 %0, %1, %2, %3;" : "=l"(d) : "l"(a), "l"(b), "l"(d));
}
__device__ __forceinline__ void mma_tf32(float* d, uint32_t a0, uint32_t a1,
                                         uint32_t a2, uint32_t a3,
                                         uint32_t b0, uint32_t b1) {
    asm volatile(
        "mma.sync.aligned.m16n8k8.row.col.f32.tf32.tf32.f32 "
        "{%0,%1,%2,%3}, {%4,%5,%6,%7}, {%8,%9}, {%0,%1,%2,%3};"
        : "+f"(d[0]), "+f"(d[1]), "+f"(d[2]), "+f"(d[3])
        : "r"(a0), "r"(a1), "r"(a2), "r"(a3), "r"(b0), "r"(b1));
}
__device__ __forceinline__ uint32_t my_ctarank() {
    uint32_t r;
    asm("mov.u32 %0, %%cluster_ctarank;" : "=r"(r));
    return r;
}
__device__ __forceinline__ uint32_t mapa_u32(uint32_t laddr, int p) {
    uint32_t ra;
    asm volatile("mapa.shared::cluster.u32 %0, %1, %2;"
                 : "=r"(ra) : "r"(laddr), "r"(p));
    return ra;
}
__device__ __forceinline__ void st_async_f32(uint32_t raddr, uint32_t rmbar,
                                             float v) {
    asm volatile(
        "st.async.shared::cluster.mbarrier::complete_tx::bytes.b32 [%0], %1, [%2];"
        :: "r"(raddr), "r"(__float_as_uint(v)), "r"(rmbar) : "memory");
}
__device__ __forceinline__ void cp_async16(uint32_t dst, const void* src) {
    asm volatile("cp.async.cg.shared.global [%0], [%1], 16;"
                 :: "r"(dst), "l"(src) : "memory");
}
#define CP_COMMIT() asm volatile("cp.async.commit_group;" ::: "memory")

#define MBAR_INIT(a, n) \
    asm volatile("mbarrier.init.shared.b64 [%0], %1;" :: "r"(a), "r"(n) : "memory")
#define MBAR_EXPECT(a, tx) \
    asm volatile("mbarrier.arrive.expect_tx.shared.b64 _, [%0], %1;" \
                 :: "r"(a), "r"(tx) : "memory")
#define MBAR_WAIT_CL(a, ph) do {                                                \
    uint32_t _m = (a), _p = (ph), _d;                                           \
    asm volatile("{ .reg .pred p; "                                             \
        "mbarrier.try_wait.parity.acquire.cluster.shared::cta.b64 p, [%1], %2;" \
        " selp.b32 %0, 1, 0, p; }" : "=r"(_d) : "r"(_m), "r"(_p) : "memory");   \
    if (!_d) {                                                                  \
        asm volatile("{ .reg .pred P1; WL%=:"                                   \
            " mbarrier.try_wait.parity.acquire.cluster.shared::cta.b64 P1, [%0], %1, 0x989680;" \
            " @P1 bra.uni WD%=; bra.uni WL%=; WD%=: }"                          \
            :: "r"(_m), "r"(_p) : "memory");                                    \
    } } while (0)

// ---------------------------------------------------------------------------
__global__ void transpose_k(const float* __restrict__ in, float* __restrict__ out) {
    __shared__ float tile[32][33];
    int r0 = blockIdx.x * 32;
    int c0 = blockIdx.y * 32;
    for (int i = threadIdx.y; i < 32; i += 8)
        tile[i][threadIdx.x] = in[(r0 + i) * NHID + (c0 + threadIdx.x)];
    __syncthreads();
    for (int i = threadIdx.y; i < 32; i += 8)
        out[(c0 + i) * G3 + (r0 + threadIdx.x)] = tile[threadIdx.x][i];
}

// ---------------------------------------------------------------------------
// tf32 mma.sync GEMM, NST-stage cp.async pipeline (templated: NST stages,
// MIN blocks/SM). Prologue commits NST-1 groups; every iter commits exactly
// one (possibly empty) group; wait_group NST-2 at iter i retires chunk i.
// ---------------------------------------------------------------------------
#define GM_THREADS 256

template<int NST, int MIN>
__global__ void __launch_bounds__(GM_THREADS, MIN)
gemm_mma_t(const float* __restrict__ A, int lda,
           const float* __restrict__ Bw, int ldb,
           const float* __restrict__ bias,
           float* __restrict__ C, int ldc,
           const int* __restrict__ tok,
           int M, int N, int K)
{
    float* smem = (float*)dsmem;
    const uint32_t sbase = smem_u32(dsmem);

    const int tid  = threadIdx.x;
    const int wid  = tid >> 5, lane = tid & 31;
    const int wm   = wid >> 1;
    const int wn   = wid & 1;
    const int gid  = lane >> 2;
    const int tig  = lane & 3;
    const int row0 = blockIdx.y * 128, col0 = blockIdx.x * 128;

    const int sr = tid >> 3;
    const int sc = (tid & 7) * 4;
    const float* Aptr[4];
    const float* Bptr[4];
#pragma unroll
    for (int ps = 0; ps < 4; ps++) {
        int ar = row0 + sr + ps * 32;
        if (ar >= M) ar = M - 1;
        if (tok) ar = tok[ar];
        Aptr[ps] = A + (size_t)ar * lda + sc;
        int br = col0 + sr + ps * 32;
        if (br >= N) br = N - 1;
        Bptr[ps] = Bw + (size_t)br * ldb + sc;
    }
    uint32_t stOff[4];
#pragma unroll
    for (int ps = 0; ps < 4; ps++) {
        int r = sr + ps * 32;
        stOff[ps] = (r * 32 + 4 * ((sc >> 2) ^ (r & 7))) * 4;  // bytes
    }

    const int NC = K >> 5;

    auto issue = [&](int idx) {
        uint32_t ab = sbase + (uint32_t)(idx % NST) * 32768u;
        const int co = idx * 32;
#pragma unroll
        for (int ps = 0; ps < 4; ps++) {
            cp_async16(ab + stOff[ps], Aptr[ps] + co);
            cp_async16(ab + 16384u + stOff[ps], Bptr[ps] + co);
        }
        CP_COMMIT();
    };

#pragma unroll
    for (int s = 0; s < NST - 1; s++) issue(s);

    float acc[2][8][4];
#pragma unroll
    for (int mt = 0; mt < 2; mt++)
#pragma unroll
        for (int nt = 0; nt < 8; nt++)
#pragma unroll
            for (int j = 0; j < 4; j++) acc[mt][nt][j] = 0.f;

    for (int i = 0; i < NC; i++) {
        asm volatile("cp.async.wait_group %0;" :: "n"(NST - 2) : "memory");
        __syncthreads();

        const float* As = smem + (size_t)(i % NST) * 8192;
        const float* Bs = As + 4096;

#pragma unroll
        for (int kk = 0; kk < 4; kk++) {
            const int s0 = 4 * (((kk * 2)    ) ^ gid);
            const int s1 = 4 * (((kk * 2) + 1) ^ gid);
            uint32_t af[2][4];
#pragma unroll
            for (int mt = 0; mt < 2; mt++) {
                int rA = wm * 32 + mt * 16 + gid;
                af[mt][0] = to_tf32_bits(As[rA * 32 + tig + s0]);
                af[mt][1] = to_tf32_bits(As[(rA + 8) * 32 + tig + s0]);
                af[mt][2] = to_tf32_bits(As[rA * 32 + tig + s1]);
                af[mt][3] = to_tf32_bits(As[(rA + 8) * 32 + tig + s1]);
            }
            uint32_t bf[8][2];
#pragma unroll
            for (int nt = 0; nt < 8; nt++) {
                int rB = wn * 64 + nt * 8 + gid;
                bf[nt][0] = to_tf32_bits(Bs[rB * 32 + tig + s0]);
                bf[nt][1] = to_tf32_bits(Bs[rB * 32 + tig + s1]);
            }
#pragma unroll
            for (int mt = 0; mt < 2; mt++)
#pragma unroll
                for (int nt = 0; nt < 8; nt++)
                    mma_tf32(acc[mt][nt], af[mt][0], af[mt][1], af[mt][2],
                             af[mt][3], bf[nt][0], bf[nt][1]);
        }

        if (i + NST - 1 < NC) issue(i + NST - 1);
        else                  CP_COMMIT();   // empty group keeps accounting uniform
    }

    // epilogue
#pragma unroll
    for (int mt = 0; mt < 2; mt++) {
        int row = row0 + wm * 32 + mt * 16 + gid;
        if (row >= M) continue;
#pragma unroll
        for (int nt = 0; nt < 8; nt++) {
            int col = col0 + wn * 64 + nt * 8 + tig * 2;
            if (col >= N) continue;
            float b0v = bias ? bias[col] : 0.f;
            float* p0 = C + (size_t)row * ldc + col;
            float* p1 = C + (size_t)(row + 8) * ldc + col;
            if (col + 1 < N) {
                float b1v = bias ? bias[col + 1] : 0.f;
                *(float2*)p0 = make_float2(acc[mt][nt][0] + b0v,
                                           acc[mt][nt][1] + b1v);
                if (row + 8 < M)
                    *(float2*)p1 = make_float2(acc[mt][nt][2] + b0v,
                                               acc[mt][nt][3] + b1v);
            } else {
                p0[0] = acc[mt][nt][0] + b0v;
                if (row + 8 < M) p1[0] = acc[mt][nt][2] + b0v;
            }
        }
    }
}

// ---------------------------------------------------------------------------
// fp32 SGEMM (small hb2 GEMM only)
// ---------------------------------------------------------------------------
__global__ void __launch_bounds__(256)
sgemm_nt(const float* __restrict__ A, int lda,
         const float* __restrict__ Bw, int ldb,
         const float* __restrict__ bias,
         float* __restrict__ C, int ldc,
         int M, int N, int K)
{
    __shared__ __align__(16) float As[8][132];
    __shared__ __align__(16) float Bs[8][128];

    const int tid  = threadIdx.x;
    const int row0 = blockIdx.y * 128;
    const int col0 = blockIdx.x * 128;

    const int li = tid >> 1;
    const int lk = (tid & 1) * 4;

    int ar = row0 + li;
    if (ar >= M) ar = M - 1;
    const float* Ap = A + (size_t)ar * lda + lk;

    int brn = col0 + li;
    const bool bval = (brn < N);
    const float* Bp = Bw + (size_t)(bval ? brn : 0) * ldb + lk;

    const int ty = tid >> 4;
    const int tx = tid & 15;

    unsigned long long acc2[8][4];
#pragma unroll
    for (int r = 0; r < 8; r++)
#pragma unroll
        for (int c = 0; c < 4; c++) acc2[r][c] = 0ull;

    for (int k0 = 0; k0 < K; k0 += 8) {
        float4 av = *(const float4*)(Ap + k0);
        float4 bv = bval ? *(const float4*)(Bp + k0) : make_float4(0.f, 0.f, 0.f, 0.f);

        __syncthreads();
        As[lk + 0][li] = av.x; As[lk + 1][li] = av.y;
        As[lk + 2][li] = av.z; As[lk + 3][li] = av.w;
        Bs[lk + 0][li] = bv.x; Bs[lk + 1][li] = bv.y;
        Bs[lk + 2][li] = bv.z; Bs[lk + 3][li] = bv.w;
        __syncthreads();

#pragma unroll
        for (int kk = 0; kk < 8; kk++) {
            float4 a0 = *(const float4*)&As[kk][ty * 8];
            float4 a1 = *(const float4*)&As[kk][ty * 8 + 4];
            const unsigned long long* bp = (const unsigned long long*)&Bs[kk][tx * 8];
            unsigned long long b0 = bp[0], b1 = bp[1], b2 = bp[2], b3 = bp[3];
            float arr[8] = {a0.x, a0.y, a0.z, a0.w, a1.x, a1.y, a1.z, a1.w};
#pragma unroll
            for (int r = 0; r < 8; r++) {
                unsigned long long ad = f2pack(arr[r], arr[r]);
                ffma2(acc2[r][0], ad, b0);
                ffma2(acc2[r][1], ad, b1);
                ffma2(acc2[r][2], ad, b2);
                ffma2(acc2[r][3], ad, b3);
            }
        }
    }

    const bool fullcol = (col0 + 128 <= N);
#pragma unroll
    for (int r = 0; r < 8; r++) {
        int row = row0 + ty * 8 + r;
        if (row >= M) continue;
        float* Cp = C + (size_t)row * ldc + col0 + tx * 8;
        float v[8];
#pragma unroll
        for (int c = 0; c < 4; c++) f2unpack(acc2[r][c], v[2 * c], v[2 * c + 1]);
        if (fullcol) {
            if (bias) {
#pragma unroll
                for (int c = 0; c < 8; c++) v[c] += bias[col0 + tx * 8 + c];
            }
            *(float4*)(Cp)     = make_float4(v[0], v[1], v[2], v[3]);
            *(float4*)(Cp + 4) = make_float4(v[4], v[5], v[6], v[7]);
        } else {
#pragma unroll
            for (int c = 0; c < 8; c++) {
                int col = col0 + tx * 8 + c;
                if (col < N) Cp[c] = v[c] + (bias ? bias[col] : 0.f);
            }
        }
    }
}

// ---------------------------------------------------------------------------
// GRU scan v6: dataflow sync. Per step each CTA pushes its 128 h values into
// all 8 cluster CTAs via st.async (tx-counted on the REMOTE mbarrier) and
// consumers wait on their local mbarrier (expect 4096 B). No per-step
// cluster rendezvous: a CTA proceeds as soon as its inputs arrive.
//
// Safety: a peer can only overwrite my hbuf[cur] after passing its own wait,
// which needs my step-t push, which follows all my reads of hbuf[cur].
//
// Smem (bytes):
//   [0,      98304)  w_s [256][3][8] float4
//   [98304, 106624)  h   [2][4][260] float
//   [106624,112768)  sgp [4kh][3q][4gb][8quad] float4
//   [112768,115840)  xs  [2][4][96] float
//   [115840,117376)  xb  [4][96]    float
//   [117376,117392)  mb  [2] mbarrier
// ---------------------------------------------------------------------------
#define SC_W   0
#define SC_H   98304
#define SC_SG  106624
#define SC_XS  112768
#define SC_XB  115840
#define SC_MB  117376
#define SC_SMEM 117408
#define HB     1040

__global__ void __launch_bounds__(SCAN_THREADS) __cluster_dims__(CL, 1, 1)
gru_cluster(const float* __restrict__ xg,
            const float* __restrict__ hb,
            const float* __restrict__ WT,
            const float* __restrict__ bhh,
            float* __restrict__ hfin,
            float* __restrict__ preds,
            float* __restrict__ tail)
{
    float4* w_s  = (float4*)(dsmem + SC_W);
    float*  hbuf = (float*) (dsmem + SC_H);
    float4* sgp4 = (float4*)(dsmem + SC_SG);
    float*  sgf  = (float*) (dsmem + SC_SG);
    float*  xs   = (float*) (dsmem + SC_XS);
    float*  xb   = (float*) (dsmem + SC_XB);

    const int tid  = threadIdx.x;
    const int cid  = blockIdx.x / CL;
    const int rank = (int)my_ctarank();
    const int b0   = cid * LP;
    const int colbase = rank * 32;

    const uint32_t mybase = smem_u32(dsmem);
    uint32_t peerbase[CL];
#pragma unroll
    for (int p = 0; p < CL; p++) peerbase[p] = mapa_u32(mybase, p);

    if (tid == 0) {
        MBAR_INIT(mybase + SC_MB, 1);
        MBAR_INIT(mybase + SC_MB + 8, 1);
    }

    for (int i = tid; i < 256 * 24; i += SCAN_THREADS) {
        int k = i / 24, j = i - 24 * k;
        int g = j >> 3, quad = j & 7;
        w_s[i] = *(const float4*)(WT + (size_t)k * G3 + g * NHID + colbase + quad * 4);
    }
    for (int i = tid; i < (2 * HB) / 4; i += SCAN_THREADS)
        ((float4*)hbuf)[i] = make_float4(0.f, 0.f, 0.f, 0.f);
    for (int i = tid; i < LP * 96; i += SCAN_THREADS) {
        int b = i / 96, j = i - 96 * b;
        int g = j >> 5, c = j & 31;
        xb[i] = hb ? hb[(size_t)(b0 + b) * G3 + g * NHID + colbase + c] : 0.f;
    }

    // GEMV mapping: tid = q*128 + kh*32 + quad*4 + gb
    const int q    = tid >> 7;
    const int r128 = tid & 127;
    const int kh   = r128 >> 5;
    const int quad = (r128 >> 2) & 7;
    const int gb   = r128 & 3;
    const int k0   = kh * 64;

    unsigned long long bhA = 0ull, bhB = 0ull;
    if (kh == 0) {
        const float4 bh4 = *(const float4*)(bhh + q * NHID + colbase + quad * 4);
        bhA = f2pack(bh4.x, bh4.y);
        bhB = f2pack(bh4.z, bh4.w);
    }

    // xg prefetch mapping (threads 0..95)
    const int pb = tid / 24;
    const int pj = tid - 24 * pb;
    const int pg = pj >> 3, pf = pj & 7;
    const bool pfv = (tid < 96);
    const float* xgp = pfv
        ? xg + (size_t)(b0 + pb) * G3 + pg * NHID + colbase + pf * 4 : xg;
    float* xss = xs + (pfv ? pb * 96 + pg * 32 + pf * 4 : 0);

    float4 v = pfv ? *(const float4*)(xgp) : make_float4(0.f, 0.f, 0.f, 0.f);
    if (pfv) {
        *(float4*)(xss) = v;
        v = *(const float4*)(xgp + (size_t)BB * G3);
    }

    __syncthreads();
    // all CTAs' mbarriers initialized before any st.async can target them
    asm volatile("barrier.cluster.arrive.aligned;" ::: "memory");
    asm volatile("barrier.cluster.wait.aligned;"   ::: "memory");

    int ph[2] = {0, 0};

    for (int t = 0; t < TT; t++) {
        const int cur = t & 1;
        const int nxt = cur ^ 1;

        if (t > 0) {
            MBAR_WAIT_CL(mybase + SC_MB + cur * 8, ph[cur]);
            if (tid == 0) {}  // (phase tracked per-thread below)
        }
        if (t > 0) ph[cur] ^= 1;
        if (tid == 0 && t < TT - 1)
            MBAR_EXPECT(mybase + SC_MB + nxt * 8, 4096);

        // ---- 4-way split-k GEMV over k in [k0, k0+64) ----
        const float* hc = hbuf + cur * HB;
        unsigned long long accA = bhA, accB = bhB;
        const float4* wp = w_s + (q * 8 + quad) + k0 * 24;
        const float*  hp = hc + gb * 260 + k0;
#pragma unroll
        for (int kk = 0; kk < 16; kk++) {
            const float4* wb = wp + (4 * kk) * 24;
            ulonglong2 w0 = *(const ulonglong2*)(wb);
            ulonglong2 w1 = *(const ulonglong2*)(wb + 24);
            ulonglong2 w2 = *(const ulonglong2*)(wb + 48);
            ulonglong2 w3 = *(const ulonglong2*)(wb + 72);
            float4 h4 = *(const float4*)(hp + 4 * kk);
            unsigned long long h0 = f2pack(h4.x, h4.x);
            unsigned long long h1 = f2pack(h4.y, h4.y);
            unsigned long long h2 = f2pack(h4.z, h4.z);
            unsigned long long h3 = f2pack(h4.w, h4.w);
            ffma2(accA, w0.x, h0); ffma2(accB, w0.y, h0);
            ffma2(accA, w1.x, h1); ffma2(accB, w1.y, h1);
            ffma2(accA, w2.x, h2); ffma2(accB, w2.y, h2);
            ffma2(accA, w3.x, h3); ffma2(accB, w3.y, h3);
        }
        float4 accv;
        f2unpack(accA, accv.x, accv.y);
        f2unpack(accB, accv.z, accv.w);
        sgp4[kh * 96 + q * 32 + gb * 8 + quad] = accv;
        __syncthreads();

        // ---- phase 2: reduce split-k, gates, update, dataflow push ----
        if (tid < LP * 32) {
            int tb = tid >> 5;
            int c  = tid & 31;
            const float* xr  = xs + cur * 384 + tb * 96;
            const float* xbr = xb + tb * 96;
            int base = tb * 32 + c;
            float hgr = sgf[base]       + sgf[384 + base]
                      + sgf[768 + base] + sgf[1152 + base];
            float hgz = sgf[128 + base]       + sgf[384 + 128 + base]
                      + sgf[768 + 128 + base] + sgf[1152 + 128 + base];
            float hgn = sgf[256 + base]       + sgf[384 + 256 + base]
                      + sgf[768 + 256 + base] + sgf[1152 + 256 + base];
            float gr = xr[c]      + xbr[c];
            float gz = xr[32 + c] + xbr[32 + c];
            float gn = xr[64 + c] + xbr[64 + c];
            float ho = hc[tb * 260 + colbase + c];
            float rr = 1.f / (1.f + __expf(-(gr + hgr)));
            float zz = 1.f / (1.f + __expf(-(gz + hgz)));
            float nn = tanhf(gn + rr * hgn);
            float hn = (1.f - zz) * nn + zz * ho;
            if (preds)
                preds[(size_t)(t * BB + b0 + tb) * NHID + colbase + c] = hn;
            if (t == TT - 1) {
                if (hfin) hfin[(size_t)(b0 + tb) * NHID + colbase + c] = hn;
                if (tail) tail[(size_t)(b0 + tb) * NHID + colbase + c] = hn;
            } else {
                uint32_t off  = SC_H + (uint32_t)(nxt * HB + tb * 260 + colbase + c) * 4;
                uint32_t moff = SC_MB + (uint32_t)nxt * 8;
#pragma unroll
                for (int p = 0; p < CL; p++)
                    st_async_f32(peerbase[p] + off, peerbase[p] + moff, hn);
            }
        }

        if (t == TT - 1) break;
        // stage next step's input gates, prefetch t+2 (off critical path)
        if (pfv) {
            *(float4*)(xss + nxt * 384) = v;
            if (t + 2 < TT)
                v = *(const float4*)(xgp + (size_t)(t + 2) * BB * G3);
        }
    }

    // keep cluster alive until all in-flight st.async traffic has landed
    asm volatile("barrier.cluster.arrive.aligned;" ::: "memory");
    asm volatile("barrier.cluster.wait.aligned;"   ::: "memory");
}

// ---------------------------------------------------------------------------
// Launcher
// ---------------------------------------------------------------------------
extern "C" void kernel_launch(void* const* d_in, const int* in_sizes, int n_in,
                              void* d_out, int out_size)
{
    const int*   tokens = (const int*)  d_in[0];
    const float* E      = (const float*)d_in[1];
    const float* Wih1   = (const float*)d_in[2];
    const float* Whh1   = (const float*)d_in[3];
    const float* bih1   = (const float*)d_in[4];
    const float* bhh1   = (const float*)d_in[5];
    const float* Wih2   = (const float*)d_in[6];
    const float* Whh2   = (const float*)d_in[7];
    const float* bih2   = (const float*)d_in[8];
    const float* bhh2   = (const float*)d_in[9];
    // d_in[10..14] dead (attention context == h1 exactly)
    const float* Wd     = (const float*)d_in[15];
    const float* bd     = (const float*)d_in[16];
    float* out = (float*)d_out;

    float *xg1, *xg2, *hb2, *h1, *preds, *WT1, *WT2;
    cudaGetSymbolAddress((void**)&xg1,   g_xg1);
    cudaGetSymbolAddress((void**)&xg2,   g_xg2);
    cudaGetSymbolAddress((void**)&hb2,   g_hb2);
    cudaGetSymbolAddress((void**)&h1,    g_h1);
    cudaGetSymbolAddress((void**)&preds, g_preds);
    cudaGetSymbolAddress((void**)&WT1,   g_WT1);
    cudaGetSymbolAddress((void**)&WT2,   g_WT2);

    cudaFuncSetAttribute(gru_cluster, cudaFuncAttributeMaxDynamicSharedMemorySize,
                         SC_SMEM);
    cudaFuncSetAttribute(gemm_mma_t<4, 1>,
                         cudaFuncAttributeMaxDynamicSharedMemorySize, 4 * 32768);
    cudaFuncSetAttribute(gemm_mma_t<3, 2>,
                         cudaFuncAttributeMaxDynamicSharedMemorySize, 3 * 32768);

    float* tail = nullptr;
    if (out_size >= MM * NVOC + BB * NHID) tail = out + (size_t)MM * NVOC;

    transpose_k<<<dim3(24, 8), dim3(32, 8)>>>(Whh1, WT1);
    transpose_k<<<dim3(24, 8), dim3(32, 8)>>>(Whh2, WT2);

    gemm_mma_t<4, 1><<<dim3(6, 64), GM_THREADS, 4 * 32768>>>(
        E, NIN, Wih1, NIN, bih1, xg1, G3, tokens, MM, G3, NIN);
    gemm_mma_t<4, 1><<<dim3(6, 64), GM_THREADS, 4 * 32768>>>(
        E, NIN, Wih2 + NHID, NHID + NIN, nullptr, xg2, G3, tokens, MM, G3, NIN);

    gru_cluster<<<NCLUST * CL, SCAN_THREADS, SC_SMEM>>>(
        xg1, nullptr, WT1, bhh1, h1, nullptr, tail);

    sgemm_nt<<<dim3(6, 1), 256>>>(h1, NHID, Wih2, NHID + NIN, bih2,
                                  hb2, G3, BB, G3, NHID);

    gru_cluster<<<NCLUST * CL, SCAN_THREADS, SC_SMEM>>>(
        xg2, hb2, WT2, bhh2, nullptr, preds, nullptr);

    // decoder: K=256, occupancy 2 (NST=3, 96KB smem, <=128 regs)
    gemm_mma_t<3, 2><<<dim3(79, 64), GM_THREADS, 3 * 32768>>>(
        preds, NHID, Wd, NHID, bd, out, NVOC, nullptr, MM, NVOC, NHID);
}